// round 9
// baseline (speedup 1.0000x reference)
#include <cuda_runtime.h>
#include <cuda_bf16.h>
#include <cuda_fp16.h>
#include <cstdint>

// Problem constants (fixed by the dataset)
#define NN     50000
#define DD     256
#define TWO_D  512
#define EE     320000

#define TILES_M      391            // ceil(50000/128)
#define TILES_TOTAL  1564           // 391 * 4
#define GEMM_GRID    296            // 148 SMs * 2 CTAs

// ---------------------------------------------------------------------------
// Scratch (static device arrays; no allocation allowed)
// ---------------------------------------------------------------------------
__device__ __half g_ABh[(size_t)NN * TWO_D];        // per-node A'|B in fp16
// Packed split layouts: [row][kchunk 0..7][hi 32 halves | lo 32 halves]
// = 512 bf16 per row = 1024 bytes (one SMEM tile row per 128-byte chunk).
__device__ __nv_bfloat16 g_zp[(size_t)NN * 512];
__device__ __nv_bfloat16 g_wp[(size_t)TWO_D * 512];
__device__ int g_idx_is64;

// ---------------------------------------------------------------------------
// Prep kernels
// ---------------------------------------------------------------------------
__global__ void detect_idx_kernel(const int* __restrict__ ei_words) {
    __shared__ int nz;
    if (threadIdx.x == 0) nz = 0;
    __syncthreads();
    int found = 0;
    #pragma unroll
    for (int i = threadIdx.x; i < 4096; i += 256) {
        int pos = 2 * (i * (EE / 4096)) + 1;
        if (ei_words[pos] != 0) found = 1;
    }
    if (found) atomicOr(&nz, 1);
    __syncthreads();
    if (threadIdx.x == 0) g_idx_is64 = (nz == 0) ? 1 : 0;
}

// Vectorized split conversion: each thread handles 4 consecutive k.
__global__ void convert_z_kernel(const float* __restrict__ z) {
    int stride = gridDim.x * blockDim.x;
    for (int i4 = blockIdx.x * blockDim.x + threadIdx.x; i4 < NN * 64; i4 += stride) {
        int n = i4 >> 6, q = i4 & 63;
        float4 v = ((const float4*)z)[i4];
        __nv_bfloat162 h01 = __nv_bfloat162(__float2bfloat16_rn(v.x), __float2bfloat16_rn(v.y));
        __nv_bfloat162 h23 = __nv_bfloat162(__float2bfloat16_rn(v.z), __float2bfloat16_rn(v.w));
        __nv_bfloat162 l01 = __nv_bfloat162(
            __float2bfloat16_rn(v.x - __bfloat162float(h01.x)),
            __float2bfloat16_rn(v.y - __bfloat162float(h01.y)));
        __nv_bfloat162 l23 = __nv_bfloat162(
            __float2bfloat16_rn(v.z - __bfloat162float(h23.x)),
            __float2bfloat16_rn(v.w - __bfloat162float(h23.y)));
        size_t base = (size_t)n * 512 + ((q >> 3) << 6) + ((q & 7) << 2);
        uint2 hi, lo;
        memcpy(&hi.x, &h01, 4); memcpy(&hi.y, &h23, 4);
        memcpy(&lo.x, &l01, 4); memcpy(&lo.y, &l23, 4);
        *(uint2*)(g_zp + base)      = hi;
        *(uint2*)(g_zp + base + 32) = lo;
    }
}

// W[j][k]: j<256 -> w1[j*512+k]; j>=256 -> w1[(j-256)*512+256+k]
__global__ void convert_w_kernel(const float* __restrict__ w1) {
    int idx = blockIdx.x * blockDim.x + threadIdx.x;  // idx = j*256 + k
    if (idx < TWO_D * DD) {
        int j = idx >> 8;
        int k = idx & 255;
        float v = (j < DD) ? w1[j * TWO_D + k] : w1[(j - DD) * TWO_D + DD + k];
        __nv_bfloat16 h = __float2bfloat16_rn(v);
        __nv_bfloat16 l = __float2bfloat16_rn(v - __bfloat162float(h));
        size_t base = (size_t)j * 512 + ((k >> 5) << 6) + (k & 31);
        g_wp[base]      = h;
        g_wp[base + 32] = l;
    }
}

// ---------------------------------------------------------------------------
// mma.sync helpers (sm_80+, target-independent)
// ---------------------------------------------------------------------------
__device__ __forceinline__ uint32_t smem_u32(const void* p) {
    uint32_t a;
    asm("{ .reg .u64 t; cvta.to.shared.u64 t, %1; cvt.u32.u64 %0, t; }" : "=r"(a) : "l"(p));
    return a;
}
__device__ __forceinline__ void ldm4(uint32_t* r, uint32_t addr) {
    asm volatile("ldmatrix.sync.aligned.m8n8.x4.shared.b16 {%0,%1,%2,%3}, [%4];"
                 : "=r"(r[0]), "=r"(r[1]), "=r"(r[2]), "=r"(r[3]) : "r"(addr));
}
__device__ __forceinline__ void mma16816(float* c, const uint32_t* a, uint32_t b0, uint32_t b1) {
    asm volatile("mma.sync.aligned.m16n8k16.row.col.f32.bf16.bf16.f32 "
                 "{%0,%1,%2,%3}, {%4,%5,%6,%7}, {%8,%9}, {%0,%1,%2,%3};"
                 : "+f"(c[0]), "+f"(c[1]), "+f"(c[2]), "+f"(c[3])
                 : "r"(a[0]), "r"(a[1]), "r"(a[2]), "r"(a[3]), "r"(b0), "r"(b1));
}
__device__ __forceinline__ void cp16(uint32_t dst, const void* src) {
    asm volatile("cp.async.cg.shared.global [%0], [%1], 16;" :: "r"(dst), "l"(src));
}

// Row layout: 128 bytes/row, swizzle: chunk c (0..7) -> c ^ (row & 7).
__device__ __forceinline__ uint32_t tile_off(int row, int c) {
    return row * 128 + ((c ^ (row & 7)) << 4);
}
__device__ __forceinline__ uint32_t ldm_addr(uint32_t base, int m, int c8, int lane) {
    int g = lane >> 3;
    int row = m + (lane & 7) + ((g & 1) << 3);
    int c = c8 + (g >> 1);
    return base + tile_off(row, c);
}

// ---------------------------------------------------------------------------
// Persistent node GEMM: g_ABh[50000,512] = fp16(z @ W^T (+ b1 cols<256))
// 296 persistent CTAs; continuous cp.async chunk stream across tiles.
// CTA tile 128x128, BK=32/chunk, 3-stage ring (96 KB), 8 warps, warp 64x32.
// 3-pass bf16 split accumulation in fp32.
// ---------------------------------------------------------------------------
#define B_REGION 49152
#define SM_GEMM_TOTAL 98304

__global__ __launch_bounds__(256, 2)
void node_gemm_mma(const float* __restrict__ b1) {
    extern __shared__ __align__(128) char smem[];
    const uint32_t sbase = smem_u32(smem);
    const int tid  = threadIdx.x;
    const int lane = tid & 31;
    const int wid  = tid >> 5;
    const int wm   = wid >> 2;        // 0..1 (64 rows)
    const int wn   = wid & 3;         // 0..3 (32 cols)
    const int bx   = blockIdx.x;

    // Per-thread cp.async constants
    const uint32_t rbase = (uint32_t)(tid >> 3);            // 0..31
    const uint32_t dstA0 = rbase * 128u +
        ((((uint32_t)tid & 7u) ^ (rbase & 7u)) << 4);       // swizzled dst, i-step 4096
    const char* zb2 = (const char*)g_zp + (((uint32_t)tid & 7u) << 4);
    const char* wb2 = (const char*)g_wp + (((uint32_t)tid & 7u) << 4);

    // Prefetch pointer state (uniform across CTA threads)
    int pf_g  = bx;
    uint32_t pf_m0 = (uint32_t)(pf_g % TILES_M) * 128u;
    uint32_t pf_j0 = (uint32_t)(pf_g / TILES_M) * 128u;
    int pf_pc = 0;
    int pf_stage = 0;

    // Prologue: issue stream chunks 0 and 1 (tile bx, pc 0..1)
    #pragma unroll
    for (int p = 0; p < 2; p++) {
        uint32_t stb = sbase + (uint32_t)pf_stage * 16384u;
        uint32_t aoff = (uint32_t)pf_pc * 128u;
        #pragma unroll
        for (int i = 0; i < 4; i++) {
            uint32_t r = rbase + 32u * i;
            uint32_t gr = pf_m0 + r; if (gr >= NN) gr = NN - 1;
            cp16(stb + dstA0 + i * 4096u, zb2 + (size_t)gr * 1024u + aoff);
        }
        #pragma unroll
        for (int i = 0; i < 4; i++) {
            uint32_t r = rbase + 32u * i;
            cp16(stb + B_REGION + dstA0 + i * 4096u,
                 wb2 + (size_t)(pf_j0 + r) * 1024u + aoff);
        }
        asm volatile("cp.async.commit_group;" ::: "memory");
        pf_pc++;
        pf_stage++;
    }

    int cur_stage = 0;

    for (int g = bx; g < TILES_TOTAL; g += GEMM_GRID) {
        const bool last_tile = (g + GEMM_GRID >= TILES_TOTAL);
        const uint32_t m0 = (uint32_t)(g % TILES_M) * 128u;
        const uint32_t j0 = (uint32_t)(g / TILES_M) * 128u;

        float acc[16][4];
        #pragma unroll
        for (int i = 0; i < 16; i++)
            #pragma unroll
            for (int q = 0; q < 4; q++) acc[i][q] = 0.f;

        #pragma unroll 1
        for (int kc = 0; kc < 8; kc++) {
            if (last_tile && kc == 7)
                asm volatile("cp.async.wait_group 0;" ::: "memory");
            else
                asm volatile("cp.async.wait_group 1;" ::: "memory");
            __syncthreads();

            // Issue next stream chunk (2 ahead) if any remain
            if (pf_g < TILES_TOTAL) {
                uint32_t stb = sbase + (uint32_t)pf_stage * 16384u;
                uint32_t aoff = (uint32_t)pf_pc * 128u;
                #pragma unroll
                for (int i = 0; i < 4; i++) {
                    uint32_t r = rbase + 32u * i;
                    uint32_t gr = pf_m0 + r; if (gr >= NN) gr = NN - 1;
                    cp16(stb + dstA0 + i * 4096u, zb2 + (size_t)gr * 1024u + aoff);
                }
                #pragma unroll
                for (int i = 0; i < 4; i++) {
                    uint32_t r = rbase + 32u * i;
                    cp16(stb + B_REGION + dstA0 + i * 4096u,
                         wb2 + (size_t)(pf_j0 + r) * 1024u + aoff);
                }
                asm volatile("cp.async.commit_group;" ::: "memory");
                if (++pf_pc == 8) {
                    pf_pc = 0;
                    pf_g += GEMM_GRID;
                    if (pf_g < TILES_TOTAL) {
                        pf_m0 = (uint32_t)(pf_g % TILES_M) * 128u;
                        pf_j0 = (uint32_t)(pf_g / TILES_M) * 128u;
                    }
                }
                pf_stage = (pf_stage == 2) ? 0 : pf_stage + 1;
            }

            const uint32_t Ab = sbase + (uint32_t)cur_stage * 16384u;
            const uint32_t Bb = Ab + B_REGION;

            #pragma unroll
            for (int kk = 0; kk < 2; kk++) {
                const int c8h = kk * 2;
                const int c8l = 4 + kk * 2;
                uint32_t ah[4][4], al[4][4], bh[2][4], bl[2][4];
                #pragma unroll
                for (int q = 0; q < 2; q++) {
                    ldm4(bh[q], ldm_addr(Bb, wn * 32 + q * 16, c8h, lane));
                    ldm4(bl[q], ldm_addr(Bb, wn * 32 + q * 16, c8l, lane));
                }
                #pragma unroll
                for (int mt = 0; mt < 4; mt++) {
                    ldm4(ah[mt], ldm_addr(Ab, wm * 64 + mt * 16, c8h, lane));
                    ldm4(al[mt], ldm_addr(Ab, wm * 64 + mt * 16, c8l, lane));
                }
                #pragma unroll
                for (int mt = 0; mt < 4; mt++)
                    #pragma unroll
                    for (int nt = 0; nt < 4; nt++) {
                        uint32_t bh0 = bh[nt >> 1][nt & 1], bh1 = bh[nt >> 1][(nt & 1) + 2];
                        uint32_t bl0 = bl[nt >> 1][nt & 1], bl1 = bl[nt >> 1][(nt & 1) + 2];
                        float* cc = acc[mt * 4 + nt];
                        mma16816(cc, ah[mt], bh0, bh1);
                        mma16816(cc, ah[mt], bl0, bl1);
                        mma16816(cc, al[mt], bh0, bh1);
                    }
            }
            cur_stage = (cur_stage == 2) ? 0 : cur_stage + 1;
        }

        // Epilogue (regs -> gmem; overlaps with next tile's in-flight loads)
        const bool has_bias = (j0 < DD);
        #pragma unroll
        for (int nt = 0; nt < 4; nt++) {
            int colg = (int)j0 + wn * 32 + nt * 8 + (lane & 3) * 2;
            float bv0 = 0.f, bv1 = 0.f;
            if (has_bias) { bv0 = __ldg(&b1[colg]); bv1 = __ldg(&b1[colg + 1]); }
            #pragma unroll
            for (int mt = 0; mt < 4; mt++) {
                float* cc = acc[mt * 4 + nt];
                int r0 = (int)m0 + wm * 64 + mt * 16 + (lane >> 2);
                if (r0 < NN)
                    *(__half2*)(g_ABh + (size_t)r0 * TWO_D + colg) =
                        __floats2half2_rn(cc[0] + bv0, cc[1] + bv1);
                if (r0 + 8 < NN)
                    *(__half2*)(g_ABh + (size_t)(r0 + 8) * TWO_D + colg) =
                        __floats2half2_rn(cc[2] + bv0, cc[3] + bv1);
            }
        }
    }
}

// ---------------------------------------------------------------------------
// Edge kernel: one warp per 2 edges per iteration (fp16 gathers).
// ---------------------------------------------------------------------------
__device__ __forceinline__ float dot8(uint4 av, uint4 cv, float4 wA, float4 wB) {
    const __half2* ah = (const __half2*)&av;
    const __half2* ch = (const __half2*)&cv;
    float2 a0 = __half22float2(ah[0]), a1 = __half22float2(ah[1]);
    float2 a2 = __half22float2(ah[2]), a3 = __half22float2(ah[3]);
    float2 c0 = __half22float2(ch[0]), c1 = __half22float2(ch[1]);
    float2 c2 = __half22float2(ch[2]), c3 = __half22float2(ch[3]);
    float acc;
    acc  = wA.x * fmaxf(a0.x + c0.x, 0.f);
    acc += wA.y * fmaxf(a0.y + c0.y, 0.f);
    acc += wA.z * fmaxf(a1.x + c1.x, 0.f);
    acc += wA.w * fmaxf(a1.y + c1.y, 0.f);
    acc += wB.x * fmaxf(a2.x + c2.x, 0.f);
    acc += wB.y * fmaxf(a2.y + c2.y, 0.f);
    acc += wB.z * fmaxf(a3.x + c3.x, 0.f);
    acc += wB.w * fmaxf(a3.y + c3.y, 0.f);
    return acc;
}

__global__ __launch_bounds__(256)
void edge_kernel(const void* __restrict__ ei_raw,
                 const float* __restrict__ w2,
                 const float* __restrict__ b2,
                 float* __restrict__ out) {
    const int lane   = threadIdx.x & 31;
    const int warp   = (blockIdx.x * blockDim.x + threadIdx.x) >> 5;
    const int nwarps = (gridDim.x * blockDim.x) >> 5;
    const int is64   = g_idx_is64;

    const float4 wA = __ldg((const float4*)w2 + 2 * lane);
    const float4 wB = __ldg((const float4*)w2 + 2 * lane + 1);
    const float  b2v = __ldg(b2);

    const int*       ei32 = (const int*)ei_raw;
    const long long* ei64 = (const long long*)ei_raw;

    for (int e0 = warp * 2; e0 < EE; e0 += nwarps * 2) {
        int s0, d0, s1, d1;
        if (is64) {
            s0 = (int)ei64[e0];     d0 = (int)ei64[EE + e0];
            s1 = (int)ei64[e0 + 1]; d1 = (int)ei64[EE + e0 + 1];
        } else {
            s0 = ei32[e0];     d0 = ei32[EE + e0];
            s1 = ei32[e0 + 1]; d1 = ei32[EE + e0 + 1];
        }
        uint4 a0 = __ldg((const uint4*)(g_ABh + (size_t)s0 * TWO_D) + lane);
        uint4 c0 = __ldg((const uint4*)(g_ABh + (size_t)d0 * TWO_D + DD) + lane);
        uint4 a1 = __ldg((const uint4*)(g_ABh + (size_t)s1 * TWO_D) + lane);
        uint4 c1 = __ldg((const uint4*)(g_ABh + (size_t)d1 * TWO_D + DD) + lane);

        float r0 = dot8(a0, c0, wA, wB);
        float r1 = dot8(a1, c1, wA, wB);

        #pragma unroll
        for (int o = 16; o > 0; o >>= 1) {
            r0 += __shfl_xor_sync(0xFFFFFFFFu, r0, o);
            r1 += __shfl_xor_sync(0xFFFFFFFFu, r1, o);
        }
        if (lane == 0) {
            out[e0]     = r0 + b2v;
            out[e0 + 1] = r1 + b2v;
        }
    }
}

// ---------------------------------------------------------------------------
extern "C" void kernel_launch(void* const* d_in, const int* in_sizes, int n_in,
                              void* d_out, int out_size) {
    const float* z  = (const float*)d_in[0];
    const void*  ei = d_in[1];
    const float* w1 = (const float*)d_in[2];
    const float* b1 = (const float*)d_in[3];
    const float* w2 = (const float*)d_in[4];
    const float* b2 = (const float*)d_in[5];
    float*       out = (float*)d_out;

    cudaFuncSetAttribute(node_gemm_mma, cudaFuncAttributeMaxDynamicSharedMemorySize,
                         SM_GEMM_TOTAL);

    detect_idx_kernel<<<1, 256>>>((const int*)ei);
    convert_z_kernel<<<4096, 256>>>(z);
    convert_w_kernel<<<(TWO_D * DD + 255) / 256, 256>>>(w1);

    node_gemm_mma<<<GEMM_GRID, 256, SM_GEMM_TOTAL>>>(b1);

    edge_kernel<<<2048, 256>>>(ei, w2, b2, out);
}

// round 10
// speedup vs baseline: 1.3582x; 1.3582x over previous
#include <cuda_runtime.h>
#include <cuda_bf16.h>
#include <cuda_fp16.h>
#include <cstdint>

// Problem constants (fixed by the dataset)
#define NN     50000
#define DD     256
#define TWO_D  512
#define EE     320000

// ---------------------------------------------------------------------------
// Scratch (static device arrays; no allocation allowed)
// ---------------------------------------------------------------------------
__device__ __half g_ABh[(size_t)NN * TWO_D];     // per-node A'|B in fp16
__device__ __half g_zf[(size_t)NN * DD];         // z in fp16, row-major [n][k]
// W packed fp16 split: [j][kc 0..7][Wh 32 | Wl 32] = 512 halves = 1024 B/row
__device__ __half g_wp[(size_t)TWO_D * 512];
__device__ int g_idx_is64;

// ---------------------------------------------------------------------------
// Prep kernels
// ---------------------------------------------------------------------------
// z -> fp16 (plain, no split). Each thread: one float4 -> 4 halves.
__global__ void convert_z_kernel(const float* __restrict__ z) {
    int stride = gridDim.x * blockDim.x;
    for (int i4 = blockIdx.x * blockDim.x + threadIdx.x; i4 < NN * 64; i4 += stride) {
        float4 v = ((const float4*)z)[i4];
        __half2 h01 = __floats2half2_rn(v.x, v.y);
        __half2 h23 = __floats2half2_rn(v.z, v.w);
        uint2 o;
        memcpy(&o.x, &h01, 4); memcpy(&o.y, &h23, 4);
        ((uint2*)g_zf)[i4] = o;
    }
}

// W[j][k]: j<256 -> w1[j*512+k]; j>=256 -> w1[(j-256)*512+256+k]
// fp16 hi/lo split packed per row. Block 0 also does edge-index dtype detect.
__global__ void convert_w_kernel(const float* __restrict__ w1,
                                 const int* __restrict__ ei_words) {
    int idx = blockIdx.x * blockDim.x + threadIdx.x;  // idx = j*256 + k
    if (idx < TWO_D * DD) {
        int j = idx >> 8;
        int k = idx & 255;
        float v = (j < DD) ? w1[j * TWO_D + k] : w1[(j - DD) * TWO_D + DD + k];
        __half h = __float2half_rn(v);
        __half l = __float2half_rn(v - __half2float(h));
        size_t base = (size_t)j * 512 + ((k >> 5) << 6) + (k & 31);
        g_wp[base]      = h;
        g_wp[base + 32] = l;
    }
    // Inline dtype detect (int64 -> odd 32-bit words all zero for idx < 2^31)
    if (blockIdx.x == 0 && threadIdx.x < 32) {
        int found = 0;
        for (int i = threadIdx.x; i < 1024; i += 32) {
            int pos = 2 * (i * (EE / 1024)) + 1;
            if (ei_words[pos] != 0) found = 1;
        }
        unsigned any = __any_sync(0xFFFFFFFFu, found);
        if (threadIdx.x == 0) g_idx_is64 = any ? 0 : 1;
    }
}

// ---------------------------------------------------------------------------
// mma.sync helpers (sm_80+, target-independent)
// ---------------------------------------------------------------------------
__device__ __forceinline__ uint32_t smem_u32(const void* p) {
    uint32_t a;
    asm("{ .reg .u64 t; cvta.to.shared.u64 t, %1; cvt.u32.u64 %0, t; }" : "=r"(a) : "l"(p));
    return a;
}
__device__ __forceinline__ void ldm4(uint32_t* r, uint32_t addr) {
    asm volatile("ldmatrix.sync.aligned.m8n8.x4.shared.b16 {%0,%1,%2,%3}, [%4];"
                 : "=r"(r[0]), "=r"(r[1]), "=r"(r[2]), "=r"(r[3]) : "r"(addr));
}
__device__ __forceinline__ void mma16816(float* c, const uint32_t* a, uint32_t b0, uint32_t b1) {
    asm volatile("mma.sync.aligned.m16n8k16.row.col.f32.f16.f16.f32 "
                 "{%0,%1,%2,%3}, {%4,%5,%6,%7}, {%8,%9}, {%0,%1,%2,%3};"
                 : "+f"(c[0]), "+f"(c[1]), "+f"(c[2]), "+f"(c[3])
                 : "r"(a[0]), "r"(a[1]), "r"(a[2]), "r"(a[3]), "r"(b0), "r"(b1));
}
__device__ __forceinline__ void cp16(uint32_t dst, const void* src) {
    asm volatile("cp.async.cg.shared.global [%0], [%1], 16;" :: "r"(dst), "l"(src));
}

// Tile: 128 rows x 128 bytes; swizzle: 16B-chunk c (0..7) -> c ^ (row & 7).
__device__ __forceinline__ uint32_t tile_off(int row, int c) {
    return row * 128 + ((c ^ (row & 7)) << 4);
}
__device__ __forceinline__ uint32_t ldm_addr(uint32_t base, int m, int c8, int lane) {
    int g = lane >> 3;
    int row = m + (lane & 7) + ((g & 1) << 3);
    int c = c8 + (g >> 1);
    return base + tile_off(row, c);
}

// ---------------------------------------------------------------------------
// Node GEMM: g_ABh[50000,512] = fp16(z @ W^T (+ b1 cols<256))
// Non-persistent grid 391x4, CTA tile 128x128. Superchunk = K 64.
// Stage (48KB): A fp16 [128x64] + B hi|lo tiles for kc=2sc,2sc+1.
// 2-stage ring (96KB). 8 warps, warp tile 64x32.
// 2-pass fp16 accumulation in fp32: C = A*Wh + A*Wl.
// ---------------------------------------------------------------------------
#define STAGE_STRIDE 49152
#define SM_GEMM_TOTAL 98304

__global__ __launch_bounds__(256, 2)
void node_gemm_mma(const float* __restrict__ b1) {
    extern __shared__ __align__(128) char smem[];
    const uint32_t sbase = smem_u32(smem);
    const int tid  = threadIdx.x;
    const int lane = tid & 31;
    const int wid  = tid >> 5;
    const int wm   = wid >> 2;        // 0..1 (64 rows)
    const int wn   = wid & 3;         // 0..3 (32 cols)
    const int m0   = blockIdx.x * 128;
    const int j0   = blockIdx.y * 128;

    // Per-thread cp.async constants (row = tid>>3, 16B chunk = tid&7)
    const uint32_t rbase = (uint32_t)(tid >> 3);            // 0..31
    const uint32_t dst0  = rbase * 128u +
        ((((uint32_t)tid & 7u) ^ (rbase & 7u)) << 4);       // swizzled dst, i-step 4096
    const char* zb2 = (const char*)g_zf + (((uint32_t)tid & 7u) << 4);
    const char* wb2 = (const char*)g_wp + (((uint32_t)tid & 7u) << 4);

    // Precompute clamped A source row bases (4 rows per thread)
    const char* asrc[4];
    #pragma unroll
    for (int i = 0; i < 4; i++) {
        uint32_t gr = (uint32_t)m0 + rbase + 32u * i;
        if (gr >= NN) gr = NN - 1;
        asrc[i] = zb2 + (size_t)gr * 512u;
    }
    const char* bsrc[4];
    #pragma unroll
    for (int i = 0; i < 4; i++)
        bsrc[i] = wb2 + (size_t)(j0 + (int)(rbase + 32u * i)) * 1024u;

    // Issue superchunk sc into stage s
    auto issue = [&](int sc, int s) {
        uint32_t stb = sbase + (uint32_t)s * STAGE_STRIDE;
        uint32_t aoff = (uint32_t)sc * 128u;     // A: 128B slice of z row
        #pragma unroll
        for (int i = 0; i < 4; i++)
            cp16(stb + dst0 + i * 4096u, asrc[i] + aoff);
        #pragma unroll
        for (int t = 0; t < 2; t++) {
            uint32_t boff = (uint32_t)(2 * sc + t) * 128u;
            uint32_t btile = stb + 16384u + (uint32_t)t * 16384u;
            #pragma unroll
            for (int i = 0; i < 4; i++)
                cp16(btile + dst0 + i * 4096u, bsrc[i] + boff);
        }
        asm volatile("cp.async.commit_group;" ::: "memory");
    };

    issue(0, 0);
    issue(1, 1);

    float acc[16][4];
    #pragma unroll
    for (int i = 0; i < 16; i++)
        #pragma unroll
        for (int q = 0; q < 4; q++) acc[i][q] = 0.f;

    #pragma unroll 1
    for (int sc = 0; sc < 4; sc++) {
        if (sc < 3) asm volatile("cp.async.wait_group 1;" ::: "memory");
        else        asm volatile("cp.async.wait_group 0;" ::: "memory");
        __syncthreads();

        const uint32_t stb = sbase + (uint32_t)(sc & 1) * STAGE_STRIDE;

        #pragma unroll
        for (int kk = 0; kk < 4; kk++) {
            const uint32_t Ab = stb;                              // A tile
            const uint32_t Bb = stb + 16384u + (uint32_t)(kk >> 1) * 16384u;
            const int c8a = 2 * kk;                 // A chunks (k16 within 64)
            const int c8h = 2 * (kk & 1);           // B hi chunks
            const int c8l = 4 + 2 * (kk & 1);       // B lo chunks

            uint32_t ah[4][4], bh[2][4], bl[2][4];
            #pragma unroll
            for (int q = 0; q < 2; q++) {
                ldm4(bh[q], ldm_addr(Bb, wn * 32 + q * 16, c8h, lane));
                ldm4(bl[q], ldm_addr(Bb, wn * 32 + q * 16, c8l, lane));
            }
            #pragma unroll
            for (int mt = 0; mt < 4; mt++)
                ldm4(ah[mt], ldm_addr(Ab, wm * 64 + mt * 16, c8a, lane));

            #pragma unroll
            for (int mt = 0; mt < 4; mt++)
                #pragma unroll
                for (int nt = 0; nt < 4; nt++) {
                    uint32_t h0 = bh[nt >> 1][nt & 1], h1 = bh[nt >> 1][(nt & 1) + 2];
                    uint32_t l0 = bl[nt >> 1][nt & 1], l1 = bl[nt >> 1][(nt & 1) + 2];
                    float* cc = acc[mt * 4 + nt];
                    mma16816(cc, ah[mt], h0, h1);
                    mma16816(cc, ah[mt], l0, l1);
                }
        }

        if (sc < 2) {
            __syncthreads();          // all warps done reading stage sc&1
            issue(sc + 2, sc & 1);
        }
    }

    // Epilogue: fp16 half2 stores (+ bias for cols < 256)
    const bool has_bias = (j0 < DD);
    #pragma unroll
    for (int nt = 0; nt < 4; nt++) {
        int colg = j0 + wn * 32 + nt * 8 + (lane & 3) * 2;
        float bv0 = 0.f, bv1 = 0.f;
        if (has_bias) { bv0 = __ldg(&b1[colg]); bv1 = __ldg(&b1[colg + 1]); }
        #pragma unroll
        for (int mt = 0; mt < 4; mt++) {
            float* cc = acc[mt * 4 + nt];
            int r0 = m0 + wm * 64 + mt * 16 + (lane >> 2);
            if (r0 < NN)
                *(__half2*)(g_ABh + (size_t)r0 * TWO_D + colg) =
                    __floats2half2_rn(cc[0] + bv0, cc[1] + bv1);
            if (r0 + 8 < NN)
                *(__half2*)(g_ABh + (size_t)(r0 + 8) * TWO_D + colg) =
                    __floats2half2_rn(cc[2] + bv0, cc[3] + bv1);
        }
    }
}

// ---------------------------------------------------------------------------
// Edge kernel: one warp per 2 edges per iteration (fp16 gathers).
//   out[e] = sum_d w2[d] * relu(A'[src][d] + B[dst][d]) + b2
// ---------------------------------------------------------------------------
__device__ __forceinline__ float dot8(uint4 av, uint4 cv, float4 wA, float4 wB) {
    const __half2* ah = (const __half2*)&av;
    const __half2* ch = (const __half2*)&cv;
    float2 a0 = __half22float2(ah[0]), a1 = __half22float2(ah[1]);
    float2 a2 = __half22float2(ah[2]), a3 = __half22float2(ah[3]);
    float2 c0 = __half22float2(ch[0]), c1 = __half22float2(ch[1]);
    float2 c2 = __half22float2(ch[2]), c3 = __half22float2(ch[3]);
    float acc;
    acc  = wA.x * fmaxf(a0.x + c0.x, 0.f);
    acc += wA.y * fmaxf(a0.y + c0.y, 0.f);
    acc += wA.z * fmaxf(a1.x + c1.x, 0.f);
    acc += wA.w * fmaxf(a1.y + c1.y, 0.f);
    acc += wB.x * fmaxf(a2.x + c2.x, 0.f);
    acc += wB.y * fmaxf(a2.y + c2.y, 0.f);
    acc += wB.z * fmaxf(a3.x + c3.x, 0.f);
    acc += wB.w * fmaxf(a3.y + c3.y, 0.f);
    return acc;
}

__global__ __launch_bounds__(256)
void edge_kernel(const void* __restrict__ ei_raw,
                 const float* __restrict__ w2,
                 const float* __restrict__ b2,
                 float* __restrict__ out) {
    const int lane   = threadIdx.x & 31;
    const int warp   = (blockIdx.x * blockDim.x + threadIdx.x) >> 5;
    const int nwarps = (gridDim.x * blockDim.x) >> 5;
    const int is64   = g_idx_is64;

    const float4 wA = __ldg((const float4*)w2 + 2 * lane);
    const float4 wB = __ldg((const float4*)w2 + 2 * lane + 1);
    const float  b2v = __ldg(b2);

    const int*       ei32 = (const int*)ei_raw;
    const long long* ei64 = (const long long*)ei_raw;

    for (int e0 = warp * 2; e0 < EE; e0 += nwarps * 2) {
        int s0, d0, s1, d1;
        if (is64) {
            s0 = (int)ei64[e0];     d0 = (int)ei64[EE + e0];
            s1 = (int)ei64[e0 + 1]; d1 = (int)ei64[EE + e0 + 1];
        } else {
            s0 = ei32[e0];     d0 = ei32[EE + e0];
            s1 = ei32[e0 + 1]; d1 = ei32[EE + e0 + 1];
        }
        uint4 a0 = __ldg((const uint4*)(g_ABh + (size_t)s0 * TWO_D) + lane);
        uint4 c0 = __ldg((const uint4*)(g_ABh + (size_t)d0 * TWO_D + DD) + lane);
        uint4 a1 = __ldg((const uint4*)(g_ABh + (size_t)s1 * TWO_D) + lane);
        uint4 c1 = __ldg((const uint4*)(g_ABh + (size_t)d1 * TWO_D + DD) + lane);

        float r0 = dot8(a0, c0, wA, wB);
        float r1 = dot8(a1, c1, wA, wB);

        #pragma unroll
        for (int o = 16; o > 0; o >>= 1) {
            r0 += __shfl_xor_sync(0xFFFFFFFFu, r0, o);
            r1 += __shfl_xor_sync(0xFFFFFFFFu, r1, o);
        }
        if (lane == 0) {
            out[e0]     = r0 + b2v;
            out[e0 + 1] = r1 + b2v;
        }
    }
}

// ---------------------------------------------------------------------------
extern "C" void kernel_launch(void* const* d_in, const int* in_sizes, int n_in,
                              void* d_out, int out_size) {
    const float* z  = (const float*)d_in[0];
    const void*  ei = d_in[1];
    const float* w1 = (const float*)d_in[2];
    const float* b1 = (const float*)d_in[3];
    const float* w2 = (const float*)d_in[4];
    const float* b2 = (const float*)d_in[5];
    float*       out = (float*)d_out;

    cudaFuncSetAttribute(node_gemm_mma, cudaFuncAttributeMaxDynamicSharedMemorySize,
                         SM_GEMM_TOTAL);

    convert_z_kernel<<<2048, 256>>>(z);
    convert_w_kernel<<<(TWO_D * DD + 255) / 256, 256>>>(w1, (const int*)ei);

    dim3 ggrid((NN + 127) / 128, 4);   // 391 x 4
    node_gemm_mma<<<ggrid, 256, SM_GEMM_TOTAL>>>(b1);

    edge_kernel<<<2048, 256>>>(ei, w2, b2, out);
}

// round 11
// speedup vs baseline: 1.7604x; 1.2961x over previous
#include <cuda_runtime.h>
#include <cuda_bf16.h>
#include <cuda_fp16.h>
#include <cstdint>

// Problem constants (fixed by the dataset)
#define NN     50000
#define DD     256
#define TWO_D  512
#define EE     320000

// ---------------------------------------------------------------------------
// Scratch (static device arrays; no allocation allowed)
// ---------------------------------------------------------------------------
__device__ __half g_ABh[(size_t)NN * TWO_D];     // per-node A'|B in fp16
__device__ __half g_zf[(size_t)NN * DD];         // z in fp16, row-major [n][k]
__device__ __half g_wf[(size_t)TWO_D * DD];      // W in fp16, row-major [j][k]
__device__ int g_idx_is64;

// ---------------------------------------------------------------------------
// Prep kernels
// ---------------------------------------------------------------------------
// z -> fp16. Each thread: one float4 -> 4 halves.
__global__ void convert_z_kernel(const float* __restrict__ z) {
    int stride = gridDim.x * blockDim.x;
    for (int i4 = blockIdx.x * blockDim.x + threadIdx.x; i4 < NN * 64; i4 += stride) {
        float4 v = ((const float4*)z)[i4];
        __half2 h01 = __floats2half2_rn(v.x, v.y);
        __half2 h23 = __floats2half2_rn(v.z, v.w);
        uint2 o;
        memcpy(&o.x, &h01, 4); memcpy(&o.y, &h23, 4);
        ((uint2*)g_zf)[i4] = o;
    }
}

// W[j][k]: j<256 -> w1[j*512+k]; j>=256 -> w1[(j-256)*512+256+k]  (plain fp16)
// Block 0 warp 0 also does edge-index dtype detect.
__global__ void convert_w_kernel(const float* __restrict__ w1,
                                 const int* __restrict__ ei_words) {
    int idx = blockIdx.x * blockDim.x + threadIdx.x;  // idx = j*256 + k
    if (idx < TWO_D * DD) {
        int j = idx >> 8;
        int k = idx & 255;
        float v = (j < DD) ? w1[j * TWO_D + k] : w1[(j - DD) * TWO_D + DD + k];
        g_wf[idx] = __float2half_rn(v);
    }
    // Inline dtype detect (int64 -> odd 32-bit words all zero for idx < 2^31)
    if (blockIdx.x == 0 && threadIdx.x < 32) {
        int found = 0;
        for (int i = threadIdx.x; i < 1024; i += 32) {
            int pos = 2 * (i * (EE / 1024)) + 1;
            if (ei_words[pos] != 0) found = 1;
        }
        unsigned any = __any_sync(0xFFFFFFFFu, found);
        if (threadIdx.x == 0) g_idx_is64 = any ? 0 : 1;
    }
}

// ---------------------------------------------------------------------------
// mma.sync helpers (sm_80+, target-independent)
// ---------------------------------------------------------------------------
__device__ __forceinline__ uint32_t smem_u32(const void* p) {
    uint32_t a;
    asm("{ .reg .u64 t; cvta.to.shared.u64 t, %1; cvt.u32.u64 %0, t; }" : "=r"(a) : "l"(p));
    return a;
}
__device__ __forceinline__ void ldm4(uint32_t* r, uint32_t addr) {
    asm volatile("ldmatrix.sync.aligned.m8n8.x4.shared.b16 {%0,%1,%2,%3}, [%4];"
                 : "=r"(r[0]), "=r"(r[1]), "=r"(r[2]), "=r"(r[3]) : "r"(addr));
}
__device__ __forceinline__ void mma16816(float* c, const uint32_t* a, uint32_t b0, uint32_t b1) {
    asm volatile("mma.sync.aligned.m16n8k16.row.col.f32.f16.f16.f32 "
                 "{%0,%1,%2,%3}, {%4,%5,%6,%7}, {%8,%9}, {%0,%1,%2,%3};"
                 : "+f"(c[0]), "+f"(c[1]), "+f"(c[2]), "+f"(c[3])
                 : "r"(a[0]), "r"(a[1]), "r"(a[2]), "r"(a[3]), "r"(b0), "r"(b1));
}
__device__ __forceinline__ void cp16(uint32_t dst, const void* src) {
    asm volatile("cp.async.cg.shared.global [%0], [%1], 16;" :: "r"(dst), "l"(src));
}

// Tile: 128 rows x 128 bytes; swizzle: 16B-chunk c (0..7) -> c ^ (row & 7).
__device__ __forceinline__ uint32_t tile_off(int row, int c) {
    return row * 128 + ((c ^ (row & 7)) << 4);
}
__device__ __forceinline__ uint32_t ldm_addr(uint32_t base, int m, int c8, int lane) {
    int g = lane >> 3;
    int row = m + (lane & 7) + ((g & 1) << 3);
    int c = c8 + (g >> 1);
    return base + tile_off(row, c);
}

// ---------------------------------------------------------------------------
// Node GEMM: g_ABh[50000,512] = fp16(z @ W^T (+ b1 cols<256))
// Non-persistent grid 391x4, CTA tile 128x128. Superchunk = K 64.
// Stage (32KB): A fp16 [128x64] + B fp16 [128x64]. 3-stage ring (96KB).
// 8 warps, warp tile 64x32. Single-pass fp16 MMA, fp32 accumulate.
// ---------------------------------------------------------------------------
#define STAGE_STRIDE 32768
#define SM_GEMM_TOTAL 98304

__global__ __launch_bounds__(256, 2)
void node_gemm_mma(const float* __restrict__ b1) {
    extern __shared__ __align__(128) char smem[];
    const uint32_t sbase = smem_u32(smem);
    const int tid  = threadIdx.x;
    const int lane = tid & 31;
    const int wid  = tid >> 5;
    const int wm   = wid >> 2;        // 0..1 (64 rows)
    const int wn   = wid & 3;         // 0..3 (32 cols)
    const int m0   = blockIdx.x * 128;
    const int j0   = blockIdx.y * 128;

    // Per-thread cp.async constants (row = tid>>3, 16B chunk = tid&7)
    const uint32_t rbase = (uint32_t)(tid >> 3);            // 0..31
    const uint32_t dst0  = rbase * 128u +
        ((((uint32_t)tid & 7u) ^ (rbase & 7u)) << 4);       // swizzled dst, i-step 4096
    const char* zb2 = (const char*)g_zf + (((uint32_t)tid & 7u) << 4);
    const char* wb2 = (const char*)g_wf + (((uint32_t)tid & 7u) << 4);

    // Precompute clamped A / B source row bases (4 rows per thread each)
    const char* asrc[4];
    #pragma unroll
    for (int i = 0; i < 4; i++) {
        uint32_t gr = (uint32_t)m0 + rbase + 32u * i;
        if (gr >= NN) gr = NN - 1;
        asrc[i] = zb2 + (size_t)gr * 512u;
    }
    const char* bsrc[4];
    #pragma unroll
    for (int i = 0; i < 4; i++)
        bsrc[i] = wb2 + (size_t)(j0 + (int)(rbase + 32u * i)) * 512u;

    // Issue superchunk sc (K columns sc*32..sc*32+31) into stage s
    auto issue = [&](int sc, int s) {
        uint32_t stb = sbase + (uint32_t)s * STAGE_STRIDE;
        uint32_t off = (uint32_t)sc * 128u;     // 128B slice of 512B row
        #pragma unroll
        for (int i = 0; i < 4; i++)
            cp16(stb + dst0 + i * 4096u, asrc[i] + off);
        #pragma unroll
        for (int i = 0; i < 4; i++)
            cp16(stb + 16384u + dst0 + i * 4096u, bsrc[i] + off);
        asm volatile("cp.async.commit_group;" ::: "memory");
    };

    issue(0, 0);
    issue(1, 1);
    issue(2, 2);

    float acc[16][4];
    #pragma unroll
    for (int i = 0; i < 16; i++)
        #pragma unroll
        for (int q = 0; q < 4; q++) acc[i][q] = 0.f;

    #pragma unroll 1
    for (int sc = 0; sc < 4; sc++) {
        // committed groups: {3,4,4,4}; need group sc done -> wait_n {2,2,1,0}
        if (sc == 0)      asm volatile("cp.async.wait_group 2;" ::: "memory");
        else if (sc == 1) asm volatile("cp.async.wait_group 2;" ::: "memory");
        else if (sc == 2) asm volatile("cp.async.wait_group 1;" ::: "memory");
        else              asm volatile("cp.async.wait_group 0;" ::: "memory");
        __syncthreads();

        const uint32_t stb = sbase + (uint32_t)(sc % 3) * STAGE_STRIDE;
        const uint32_t Ab = stb;
        const uint32_t Bb = stb + 16384u;

        #pragma unroll
        for (int kk = 0; kk < 4; kk++) {
            const int c8 = 2 * kk;
            uint32_t ah[4][4], bh[2][4];
            #pragma unroll
            for (int q = 0; q < 2; q++)
                ldm4(bh[q], ldm_addr(Bb, wn * 32 + q * 16, c8, lane));
            #pragma unroll
            for (int mt = 0; mt < 4; mt++)
                ldm4(ah[mt], ldm_addr(Ab, wm * 64 + mt * 16, c8, lane));

            #pragma unroll
            for (int mt = 0; mt < 4; mt++)
                #pragma unroll
                for (int nt = 0; nt < 4; nt++) {
                    uint32_t h0 = bh[nt >> 1][nt & 1], h1 = bh[nt >> 1][(nt & 1) + 2];
                    mma16816(acc[mt * 4 + nt], ah[mt], h0, h1);
                }
        }

        if (sc == 0) {
            __syncthreads();          // all warps done reading stage 0
            issue(3, 0);
        }
    }

    // Epilogue: fp16 half2 stores (+ bias for cols < 256)
    const bool has_bias = (j0 < DD);
    #pragma unroll
    for (int nt = 0; nt < 4; nt++) {
        int colg = j0 + wn * 32 + nt * 8 + (lane & 3) * 2;
        float bv0 = 0.f, bv1 = 0.f;
        if (has_bias) { bv0 = __ldg(&b1[colg]); bv1 = __ldg(&b1[colg + 1]); }
        #pragma unroll
        for (int mt = 0; mt < 4; mt++) {
            float* cc = acc[mt * 4 + nt];
            int r0 = m0 + wm * 64 + mt * 16 + (lane >> 2);
            if (r0 < NN)
                *(__half2*)(g_ABh + (size_t)r0 * TWO_D + colg) =
                    __floats2half2_rn(cc[0] + bv0, cc[1] + bv1);
            if (r0 + 8 < NN)
                *(__half2*)(g_ABh + (size_t)(r0 + 8) * TWO_D + colg) =
                    __floats2half2_rn(cc[2] + bv0, cc[3] + bv1);
        }
    }
}

// ---------------------------------------------------------------------------
// Edge kernel: one warp per 2 edges per iteration (fp16 gathers).
//   out[e] = sum_d w2[d] * relu(A'[src][d] + B[dst][d]) + b2
// ---------------------------------------------------------------------------
__device__ __forceinline__ float dot8(uint4 av, uint4 cv, float4 wA, float4 wB) {
    const __half2* ah = (const __half2*)&av;
    const __half2* ch = (const __half2*)&cv;
    float2 a0 = __half22float2(ah[0]), a1 = __half22float2(ah[1]);
    float2 a2 = __half22float2(ah[2]), a3 = __half22float2(ah[3]);
    float2 c0 = __half22float2(ch[0]), c1 = __half22float2(ch[1]);
    float2 c2 = __half22float2(ch[2]), c3 = __half22float2(ch[3]);
    float acc;
    acc  = wA.x * fmaxf(a0.x + c0.x, 0.f);
    acc += wA.y * fmaxf(a0.y + c0.y, 0.f);
    acc += wA.z * fmaxf(a1.x + c1.x, 0.f);
    acc += wA.w * fmaxf(a1.y + c1.y, 0.f);
    acc += wB.x * fmaxf(a2.x + c2.x, 0.f);
    acc += wB.y * fmaxf(a2.y + c2.y, 0.f);
    acc += wB.z * fmaxf(a3.x + c3.x, 0.f);
    acc += wB.w * fmaxf(a3.y + c3.y, 0.f);
    return acc;
}

__global__ __launch_bounds__(256)
void edge_kernel(const void* __restrict__ ei_raw,
                 const float* __restrict__ w2,
                 const float* __restrict__ b2,
                 float* __restrict__ out) {
    const int lane   = threadIdx.x & 31;
    const int warp   = (blockIdx.x * blockDim.x + threadIdx.x) >> 5;
    const int nwarps = (gridDim.x * blockDim.x) >> 5;
    const int is64   = g_idx_is64;

    const float4 wA = __ldg((const float4*)w2 + 2 * lane);
    const float4 wB = __ldg((const float4*)w2 + 2 * lane + 1);
    const float  b2v = __ldg(b2);

    const int*       ei32 = (const int*)ei_raw;
    const long long* ei64 = (const long long*)ei_raw;

    for (int e0 = warp * 2; e0 < EE; e0 += nwarps * 2) {
        int s0, d0, s1, d1;
        if (is64) {
            s0 = (int)ei64[e0];     d0 = (int)ei64[EE + e0];
            s1 = (int)ei64[e0 + 1]; d1 = (int)ei64[EE + e0 + 1];
        } else {
            s0 = ei32[e0];     d0 = ei32[EE + e0];
            s1 = ei32[e0 + 1]; d1 = ei32[EE + e0 + 1];
        }
        uint4 a0 = __ldg((const uint4*)(g_ABh + (size_t)s0 * TWO_D) + lane);
        uint4 c0 = __ldg((const uint4*)(g_ABh + (size_t)d0 * TWO_D + DD) + lane);
        uint4 a1 = __ldg((const uint4*)(g_ABh + (size_t)s1 * TWO_D) + lane);
        uint4 c1 = __ldg((const uint4*)(g_ABh + (size_t)d1 * TWO_D + DD) + lane);

        float r0 = dot8(a0, c0, wA, wB);
        float r1 = dot8(a1, c1, wA, wB);

        #pragma unroll
        for (int o = 16; o > 0; o >>= 1) {
            r0 += __shfl_xor_sync(0xFFFFFFFFu, r0, o);
            r1 += __shfl_xor_sync(0xFFFFFFFFu, r1, o);
        }
        if (lane == 0) {
            out[e0]     = r0 + b2v;
            out[e0 + 1] = r1 + b2v;
        }
    }
}

// ---------------------------------------------------------------------------
extern "C" void kernel_launch(void* const* d_in, const int* in_sizes, int n_in,
                              void* d_out, int out_size) {
    const float* z  = (const float*)d_in[0];
    const void*  ei = d_in[1];
    const float* w1 = (const float*)d_in[2];
    const float* b1 = (const float*)d_in[3];
    const float* w2 = (const float*)d_in[4];
    const float* b2 = (const float*)d_in[5];
    float*       out = (float*)d_out;

    cudaFuncSetAttribute(node_gemm_mma, cudaFuncAttributeMaxDynamicSharedMemorySize,
                         SM_GEMM_TOTAL);

    convert_z_kernel<<<2048, 256>>>(z);
    convert_w_kernel<<<(TWO_D * DD + 255) / 256, 256>>>(w1, (const int*)ei);

    dim3 ggrid((NN + 127) / 128, 4);   // 391 x 4
    node_gemm_mma<<<ggrid, 256, SM_GEMM_TOTAL>>>(b1);

    edge_kernel<<<2048, 256>>>(ei, w2, b2, out);
}

// round 12
// speedup vs baseline: 1.7933x; 1.0187x over previous
#include <cuda_runtime.h>
#include <cuda_bf16.h>
#include <cuda_fp16.h>
#include <cstdint>

// Problem constants (fixed by the dataset)
#define NN     50000
#define DD     256
#define TWO_D  512
#define EE     320000

// ---------------------------------------------------------------------------
// Scratch (static device arrays; no allocation allowed)
// ---------------------------------------------------------------------------
__device__ __half g_ABh[(size_t)NN * TWO_D];     // per-node A'|B in fp16
__device__ __half g_zf[(size_t)NN * DD];         // z in fp16, row-major [n][k]
__device__ __half g_wf[(size_t)TWO_D * DD];      // W in fp16, row-major [j][k]
__device__ int g_idx_is64;

// ---------------------------------------------------------------------------
// Prep kernels
// ---------------------------------------------------------------------------
__global__ void convert_z_kernel(const float* __restrict__ z) {
    int stride = gridDim.x * blockDim.x;
    for (int i4 = blockIdx.x * blockDim.x + threadIdx.x; i4 < NN * 64; i4 += stride) {
        float4 v = ((const float4*)z)[i4];
        __half2 h01 = __floats2half2_rn(v.x, v.y);
        __half2 h23 = __floats2half2_rn(v.z, v.w);
        uint2 o;
        memcpy(&o.x, &h01, 4); memcpy(&o.y, &h23, 4);
        ((uint2*)g_zf)[i4] = o;
    }
}

// W[j][k]: j<256 -> w1[j*512+k]; j>=256 -> w1[(j-256)*512+256+k]  (plain fp16)
// Block 0 warp 0 also does edge-index dtype detect.
__global__ void convert_w_kernel(const float* __restrict__ w1,
                                 const int* __restrict__ ei_words) {
    int idx = blockIdx.x * blockDim.x + threadIdx.x;  // idx = j*256 + k
    if (idx < TWO_D * DD) {
        int j = idx >> 8;
        int k = idx & 255;
        float v = (j < DD) ? w1[j * TWO_D + k] : w1[(j - DD) * TWO_D + DD + k];
        g_wf[idx] = __float2half_rn(v);
    }
    if (blockIdx.x == 0 && threadIdx.x < 32) {
        int found = 0;
        for (int i = threadIdx.x; i < 1024; i += 32) {
            int pos = 2 * (i * (EE / 1024)) + 1;
            if (ei_words[pos] != 0) found = 1;
        }
        unsigned any = __any_sync(0xFFFFFFFFu, found);
        if (threadIdx.x == 0) g_idx_is64 = any ? 0 : 1;
    }
}

// ---------------------------------------------------------------------------
// mma.sync helpers (sm_80+, target-independent)
// ---------------------------------------------------------------------------
__device__ __forceinline__ uint32_t smem_u32(const void* p) {
    uint32_t a;
    asm("{ .reg .u64 t; cvta.to.shared.u64 t, %1; cvt.u32.u64 %0, t; }" : "=r"(a) : "l"(p));
    return a;
}
__device__ __forceinline__ void ldm4(uint32_t* r, uint32_t addr) {
    asm volatile("ldmatrix.sync.aligned.m8n8.x4.shared.b16 {%0,%1,%2,%3}, [%4];"
                 : "=r"(r[0]), "=r"(r[1]), "=r"(r[2]), "=r"(r[3]) : "r"(addr));
}
__device__ __forceinline__ void mma16816(float* c, const uint32_t* a, uint32_t b0, uint32_t b1) {
    asm volatile("mma.sync.aligned.m16n8k16.row.col.f32.f16.f16.f32 "
                 "{%0,%1,%2,%3}, {%4,%5,%6,%7}, {%8,%9}, {%0,%1,%2,%3};"
                 : "+f"(c[0]), "+f"(c[1]), "+f"(c[2]), "+f"(c[3])
                 : "r"(a[0]), "r"(a[1]), "r"(a[2]), "r"(a[3]), "r"(b0), "r"(b1));
}
__device__ __forceinline__ void cp16(uint32_t dst, const void* src) {
    asm volatile("cp.async.cg.shared.global [%0], [%1], 16;" :: "r"(dst), "l"(src));
}

__device__ __forceinline__ uint32_t tile_off(int row, int c) {
    return row * 128 + ((c ^ (row & 7)) << 4);
}
__device__ __forceinline__ uint32_t ldm_addr(uint32_t base, int m, int c8, int lane) {
    int g = lane >> 3;
    int row = m + (lane & 7) + ((g & 1) << 3);
    int c = c8 + (g >> 1);
    return base + tile_off(row, c);
}

// ---------------------------------------------------------------------------
// Node GEMM: g_ABh[50000,512] = fp16(z @ W^T (+ b1 cols<256))
// Grid 391x4, CTA tile 128x128. Superchunk = K 64. Stage 32KB, 3-stage ring.
// 8 warps, warp tile 64x32. Single-pass fp16 MMA, fp32 accumulate.
// ---------------------------------------------------------------------------
#define STAGE_STRIDE 32768
#define SM_GEMM_TOTAL 98304

__global__ __launch_bounds__(256, 2)
void node_gemm_mma(const float* __restrict__ b1) {
    extern __shared__ __align__(128) char smem[];
    const uint32_t sbase = smem_u32(smem);
    const int tid  = threadIdx.x;
    const int lane = tid & 31;
    const int wid  = tid >> 5;
    const int wm   = wid >> 2;
    const int wn   = wid & 3;
    const int m0   = blockIdx.x * 128;
    const int j0   = blockIdx.y * 128;

    const uint32_t rbase = (uint32_t)(tid >> 3);
    const uint32_t dst0  = rbase * 128u +
        ((((uint32_t)tid & 7u) ^ (rbase & 7u)) << 4);
    const char* zb2 = (const char*)g_zf + (((uint32_t)tid & 7u) << 4);
    const char* wb2 = (const char*)g_wf + (((uint32_t)tid & 7u) << 4);

    const char* asrc[4];
    #pragma unroll
    for (int i = 0; i < 4; i++) {
        uint32_t gr = (uint32_t)m0 + rbase + 32u * i;
        if (gr >= NN) gr = NN - 1;
        asrc[i] = zb2 + (size_t)gr * 512u;
    }
    const char* bsrc[4];
    #pragma unroll
    for (int i = 0; i < 4; i++)
        bsrc[i] = wb2 + (size_t)(j0 + (int)(rbase + 32u * i)) * 512u;

    auto issue = [&](int sc, int s) {
        uint32_t stb = sbase + (uint32_t)s * STAGE_STRIDE;
        uint32_t off = (uint32_t)sc * 128u;
        #pragma unroll
        for (int i = 0; i < 4; i++)
            cp16(stb + dst0 + i * 4096u, asrc[i] + off);
        #pragma unroll
        for (int i = 0; i < 4; i++)
            cp16(stb + 16384u + dst0 + i * 4096u, bsrc[i] + off);
        asm volatile("cp.async.commit_group;" ::: "memory");
    };

    issue(0, 0);
    issue(1, 1);
    issue(2, 2);

    float acc[16][4];
    #pragma unroll
    for (int i = 0; i < 16; i++)
        #pragma unroll
        for (int q = 0; q < 4; q++) acc[i][q] = 0.f;

    #pragma unroll 1
    for (int sc = 0; sc < 4; sc++) {
        if (sc == 0)      asm volatile("cp.async.wait_group 2;" ::: "memory");
        else if (sc == 1) asm volatile("cp.async.wait_group 2;" ::: "memory");
        else if (sc == 2) asm volatile("cp.async.wait_group 1;" ::: "memory");
        else              asm volatile("cp.async.wait_group 0;" ::: "memory");
        __syncthreads();

        const uint32_t stb = sbase + (uint32_t)(sc % 3) * STAGE_STRIDE;
        const uint32_t Ab = stb;
        const uint32_t Bb = stb + 16384u;

        #pragma unroll
        for (int kk = 0; kk < 4; kk++) {
            const int c8 = 2 * kk;
            uint32_t ah[4][4], bh[2][4];
            #pragma unroll
            for (int q = 0; q < 2; q++)
                ldm4(bh[q], ldm_addr(Bb, wn * 32 + q * 16, c8, lane));
            #pragma unroll
            for (int mt = 0; mt < 4; mt++)
                ldm4(ah[mt], ldm_addr(Ab, wm * 64 + mt * 16, c8, lane));

            #pragma unroll
            for (int mt = 0; mt < 4; mt++)
                #pragma unroll
                for (int nt = 0; nt < 4; nt++) {
                    uint32_t h0 = bh[nt >> 1][nt & 1], h1 = bh[nt >> 1][(nt & 1) + 2];
                    mma16816(acc[mt * 4 + nt], ah[mt], h0, h1);
                }
        }

        if (sc == 0) {
            __syncthreads();
            issue(3, 0);
        }
    }

    const bool has_bias = (j0 < DD);
    #pragma unroll
    for (int nt = 0; nt < 4; nt++) {
        int colg = j0 + wn * 32 + nt * 8 + (lane & 3) * 2;
        float bv0 = 0.f, bv1 = 0.f;
        if (has_bias) { bv0 = __ldg(&b1[colg]); bv1 = __ldg(&b1[colg + 1]); }
        #pragma unroll
        for (int mt = 0; mt < 4; mt++) {
            float* cc = acc[mt * 4 + nt];
            int r0 = m0 + wm * 64 + mt * 16 + (lane >> 2);
            if (r0 < NN)
                *(__half2*)(g_ABh + (size_t)r0 * TWO_D + colg) =
                    __floats2half2_rn(cc[0] + bv0, cc[1] + bv1);
            if (r0 + 8 < NN)
                *(__half2*)(g_ABh + (size_t)(r0 + 8) * TWO_D + colg) =
                    __floats2half2_rn(cc[2] + bv0, cc[3] + bv1);
        }
    }
}

// ---------------------------------------------------------------------------
// Edge kernel: 4 edges per warp iteration.
//   out[e] = sum_d w2[d] * relu(A'[src][d] + B[dst][d]) + b2
// Loads 2x2 (MLP 4), folded reduction: 11 shuffles per 4 edges.
// ---------------------------------------------------------------------------
__device__ __forceinline__ float dot8(uint4 av, uint4 cv, float4 wA, float4 wB) {
    const __half2* ah = (const __half2*)&av;
    const __half2* ch = (const __half2*)&cv;
    float2 a0 = __half22float2(ah[0]), a1 = __half22float2(ah[1]);
    float2 a2 = __half22float2(ah[2]), a3 = __half22float2(ah[3]);
    float2 c0 = __half22float2(ch[0]), c1 = __half22float2(ch[1]);
    float2 c2 = __half22float2(ch[2]), c3 = __half22float2(ch[3]);
    float acc;
    acc  = wA.x * fmaxf(a0.x + c0.x, 0.f);
    acc += wA.y * fmaxf(a0.y + c0.y, 0.f);
    acc += wA.z * fmaxf(a1.x + c1.x, 0.f);
    acc += wA.w * fmaxf(a1.y + c1.y, 0.f);
    acc += wB.x * fmaxf(a2.x + c2.x, 0.f);
    acc += wB.y * fmaxf(a2.y + c2.y, 0.f);
    acc += wB.z * fmaxf(a3.x + c3.x, 0.f);
    acc += wB.w * fmaxf(a3.y + c3.y, 0.f);
    return acc;
}

template <bool IS64>
__device__ __forceinline__ void edge_loop(const void* ei_raw,
                                          const float* w2,
                                          const float* b2,
                                          float* out,
                                          int lane, int warp, int nwarps) {
    const float4 wA = __ldg((const float4*)w2 + 2 * lane);
    const float4 wB = __ldg((const float4*)w2 + 2 * lane + 1);
    const float  b2v = __ldg(b2);

    const int*       ei32 = (const int*)ei_raw;
    const long long* ei64 = (const long long*)ei_raw;

    const int q = lane >> 3;           // 0..3: which edge this lane reduces
    const bool writer = (lane & 7) == 0;

    // EE % 4 == 0, so e0..e0+3 always valid.
    for (int e0 = warp * 4; e0 < EE; e0 += nwarps * 4) {
        int s[4], d[4];
        #pragma unroll
        for (int u = 0; u < 4; u++) {
            if (IS64) { s[u] = (int)ei64[e0 + u]; d[u] = (int)ei64[EE + e0 + u]; }
            else      { s[u] = ei32[e0 + u];      d[u] = ei32[EE + e0 + u]; }
        }

        // Pair 0: edges 0,1
        uint4 a0 = __ldg((const uint4*)(g_ABh + (size_t)s[0] * TWO_D) + lane);
        uint4 c0 = __ldg((const uint4*)(g_ABh + (size_t)d[0] * TWO_D + DD) + lane);
        uint4 a1 = __ldg((const uint4*)(g_ABh + (size_t)s[1] * TWO_D) + lane);
        uint4 c1 = __ldg((const uint4*)(g_ABh + (size_t)d[1] * TWO_D + DD) + lane);
        float r0 = dot8(a0, c0, wA, wB);
        float r1 = dot8(a1, c1, wA, wB);

        // Pair 1: edges 2,3
        uint4 a2 = __ldg((const uint4*)(g_ABh + (size_t)s[2] * TWO_D) + lane);
        uint4 c2 = __ldg((const uint4*)(g_ABh + (size_t)d[2] * TWO_D + DD) + lane);
        uint4 a3 = __ldg((const uint4*)(g_ABh + (size_t)s[3] * TWO_D) + lane);
        uint4 c3 = __ldg((const uint4*)(g_ABh + (size_t)d[3] * TWO_D + DD) + lane);
        float r2 = dot8(a2, c2, wA, wB);
        float r3 = dot8(a3, c3, wA, wB);

        // Fold 16 and 8 on each partial (each lane: sum over {l, l^8, l^16, l^24})
        r0 += __shfl_xor_sync(0xFFFFFFFFu, r0, 16);
        r1 += __shfl_xor_sync(0xFFFFFFFFu, r1, 16);
        r2 += __shfl_xor_sync(0xFFFFFFFFu, r2, 16);
        r3 += __shfl_xor_sync(0xFFFFFFFFu, r3, 16);
        r0 += __shfl_xor_sync(0xFFFFFFFFu, r0, 8);
        r1 += __shfl_xor_sync(0xFFFFFFFFu, r1, 8);
        r2 += __shfl_xor_sync(0xFFFFFFFFu, r2, 8);
        r3 += __shfl_xor_sync(0xFFFFFFFFu, r3, 8);

        // Lane-group select: lanes 0-7 finish r0, 8-15 r1, 16-23 r2, 24-31 r3
        float val = (q == 0) ? r0 : (q == 1) ? r1 : (q == 2) ? r2 : r3;
        val += __shfl_xor_sync(0xFFFFFFFFu, val, 4);
        val += __shfl_xor_sync(0xFFFFFFFFu, val, 2);
        val += __shfl_xor_sync(0xFFFFFFFFu, val, 1);

        if (writer) out[e0 + q] = val + b2v;   // lanes 0,8,16,24 -> 16B contiguous
    }
}

__global__ __launch_bounds__(256)
void edge_kernel(const void* __restrict__ ei_raw,
                 const float* __restrict__ w2,
                 const float* __restrict__ b2,
                 float* __restrict__ out) {
    const int lane   = threadIdx.x & 31;
    const int warp   = (blockIdx.x * blockDim.x + threadIdx.x) >> 5;
    const int nwarps = (gridDim.x * blockDim.x) >> 5;

    if (g_idx_is64)
        edge_loop<true>(ei_raw, w2, b2, out, lane, warp, nwarps);
    else
        edge_loop<false>(ei_raw, w2, b2, out, lane, warp, nwarps);
}

// ---------------------------------------------------------------------------
extern "C" void kernel_launch(void* const* d_in, const int* in_sizes, int n_in,
                              void* d_out, int out_size) {
    const float* z  = (const float*)d_in[0];
    const void*  ei = d_in[1];
    const float* w1 = (const float*)d_in[2];
    const float* b1 = (const float*)d_in[3];
    const float* w2 = (const float*)d_in[4];
    const float* b2 = (const float*)d_in[5];
    float*       out = (float*)d_out;

    cudaFuncSetAttribute(node_gemm_mma, cudaFuncAttributeMaxDynamicSharedMemorySize,
                         SM_GEMM_TOTAL);

    convert_z_kernel<<<2048, 256>>>(z);
    convert_w_kernel<<<(TWO_D * DD + 255) / 256, 256>>>(w1, (const int*)ei);

    dim3 ggrid((NN + 127) / 128, 4);   // 391 x 4
    node_gemm_mma<<<ggrid, 256, SM_GEMM_TOTAL>>>(b1);

    edge_kernel<<<2048, 256>>>(ei, w2, b2, out);
}

// round 13
// speedup vs baseline: 1.8793x; 1.0480x over previous
#include <cuda_runtime.h>
#include <cuda_bf16.h>
#include <cuda_fp16.h>
#include <cstdint>

// Problem constants (fixed by the dataset)
#define NN     50000
#define DD     256
#define TWO_D  512
#define EE     320000

// ---------------------------------------------------------------------------
// Scratch (static device arrays; no allocation allowed)
// ---------------------------------------------------------------------------
__device__ __half g_ABh[(size_t)NN * TWO_D];     // per-node A'|B in fp16
__device__ __half g_zf[(size_t)NN * DD];         // z in fp16, row-major [n][k]
__device__ __half g_wf[(size_t)TWO_D * DD];      // W in fp16, row-major [j][k]
__device__ int g_idx_is64;

// ---------------------------------------------------------------------------
// Fused prep kernel: z->fp16, W->fp16 (gathered layout), dtype detect.
// ---------------------------------------------------------------------------
#define ZT (NN * 64)        // z float4 count: 3,200,000
#define WT (TWO_D * 64)     // W float4 count: 32,768

__global__ void convert_all_kernel(const float* __restrict__ z,
                                   const float* __restrict__ w1,
                                   const int* __restrict__ ei_words) {
    int stride = gridDim.x * blockDim.x;
    for (int i = blockIdx.x * blockDim.x + threadIdx.x; i < ZT + WT; i += stride) {
        if (i < ZT) {
            float4 v = ((const float4*)z)[i];
            __half2 h01 = __floats2half2_rn(v.x, v.y);
            __half2 h23 = __floats2half2_rn(v.z, v.w);
            uint2 o;
            memcpy(&o.x, &h01, 4); memcpy(&o.y, &h23, 4);
            ((uint2*)g_zf)[i] = o;
        } else {
            int i4 = i - ZT;
            int j  = i4 >> 6;           // 0..511
            int k  = (i4 & 63) << 2;    // 0..252 step 4
            // W[j][k..k+3]: j<256 -> w1[j*512+k]; j>=256 -> w1[(j-256)*512+256+k]
            const float* src = (j < DD) ? (w1 + (size_t)j * TWO_D + k)
                                        : (w1 + (size_t)(j - DD) * TWO_D + DD + k);
            float4 v = *(const float4*)src;
            __half2 h01 = __floats2half2_rn(v.x, v.y);
            __half2 h23 = __floats2half2_rn(v.z, v.w);
            uint2 o;
            memcpy(&o.x, &h01, 4); memcpy(&o.y, &h23, 4);
            ((uint2*)g_wf)[i4] = o;
        }
    }
    // Inline dtype detect (int64 -> odd 32-bit words all zero for idx < 2^31)
    if (blockIdx.x == 0 && threadIdx.x < 32) {
        int found = 0;
        for (int i = threadIdx.x; i < 1024; i += 32) {
            int pos = 2 * (i * (EE / 1024)) + 1;
            if (ei_words[pos] != 0) found = 1;
        }
        unsigned any = __any_sync(0xFFFFFFFFu, found);
        if (threadIdx.x == 0) g_idx_is64 = any ? 0 : 1;
    }
}

// ---------------------------------------------------------------------------
// mma.sync helpers (sm_80+, target-independent)
// ---------------------------------------------------------------------------
__device__ __forceinline__ uint32_t smem_u32(const void* p) {
    uint32_t a;
    asm("{ .reg .u64 t; cvta.to.shared.u64 t, %1; cvt.u32.u64 %0, t; }" : "=r"(a) : "l"(p));
    return a;
}
__device__ __forceinline__ void ldm4(uint32_t* r, uint32_t addr) {
    asm volatile("ldmatrix.sync.aligned.m8n8.x4.shared.b16 {%0,%1,%2,%3}, [%4];"
                 : "=r"(r[0]), "=r"(r[1]), "=r"(r[2]), "=r"(r[3]) : "r"(addr));
}
__device__ __forceinline__ void mma16816(float* c, const uint32_t* a, uint32_t b0, uint32_t b1) {
    asm volatile("mma.sync.aligned.m16n8k16.row.col.f32.f16.f16.f32 "
                 "{%0,%1,%2,%3}, {%4,%5,%6,%7}, {%8,%9}, {%0,%1,%2,%3};"
                 : "+f"(c[0]), "+f"(c[1]), "+f"(c[2]), "+f"(c[3])
                 : "r"(a[0]), "r"(a[1]), "r"(a[2]), "r"(a[3]), "r"(b0), "r"(b1));
}
__device__ __forceinline__ void cp16(uint32_t dst, const void* src) {
    asm volatile("cp.async.cg.shared.global [%0], [%1], 16;" :: "r"(dst), "l"(src));
}

__device__ __forceinline__ uint32_t tile_off(int row, int c) {
    return row * 128 + ((c ^ (row & 7)) << 4);
}
__device__ __forceinline__ uint32_t ldm_addr(uint32_t base, int m, int c8, int lane) {
    int g = lane >> 3;
    int row = m + (lane & 7) + ((g & 1) << 3);
    int c = c8 + (g >> 1);
    return base + tile_off(row, c);
}

// ---------------------------------------------------------------------------
// Node GEMM: g_ABh[50000,512] = fp16(z @ W^T (+ b1 cols<256))
// Grid 391x4, CTA tile 128x128. Superchunk = K 64. Stage 32KB, 3-stage ring.
// 8 warps, warp tile 64x32. Single-pass fp16 MMA, fp32 accumulate.
// ---------------------------------------------------------------------------
#define STAGE_STRIDE 32768
#define SM_GEMM_TOTAL 98304

__global__ __launch_bounds__(256, 2)
void node_gemm_mma(const float* __restrict__ b1) {
    extern __shared__ __align__(128) char smem[];
    const uint32_t sbase = smem_u32(smem);
    const int tid  = threadIdx.x;
    const int lane = tid & 31;
    const int wid  = tid >> 5;
    const int wm   = wid >> 2;
    const int wn   = wid & 3;
    const int m0   = blockIdx.x * 128;
    const int j0   = blockIdx.y * 128;

    const uint32_t rbase = (uint32_t)(tid >> 3);
    const uint32_t dst0  = rbase * 128u +
        ((((uint32_t)tid & 7u) ^ (rbase & 7u)) << 4);
    const char* zb2 = (const char*)g_zf + (((uint32_t)tid & 7u) << 4);
    const char* wb2 = (const char*)g_wf + (((uint32_t)tid & 7u) << 4);

    const char* asrc[4];
    #pragma unroll
    for (int i = 0; i < 4; i++) {
        uint32_t gr = (uint32_t)m0 + rbase + 32u * i;
        if (gr >= NN) gr = NN - 1;
        asrc[i] = zb2 + (size_t)gr * 512u;
    }
    const char* bsrc[4];
    #pragma unroll
    for (int i = 0; i < 4; i++)
        bsrc[i] = wb2 + (size_t)(j0 + (int)(rbase + 32u * i)) * 512u;

    auto issue = [&](int sc, int s) {
        uint32_t stb = sbase + (uint32_t)s * STAGE_STRIDE;
        uint32_t off = (uint32_t)sc * 128u;
        #pragma unroll
        for (int i = 0; i < 4; i++)
            cp16(stb + dst0 + i * 4096u, asrc[i] + off);
        #pragma unroll
        for (int i = 0; i < 4; i++)
            cp16(stb + 16384u + dst0 + i * 4096u, bsrc[i] + off);
        asm volatile("cp.async.commit_group;" ::: "memory");
    };

    issue(0, 0);
    issue(1, 1);
    issue(2, 2);

    float acc[16][4];
    #pragma unroll
    for (int i = 0; i < 16; i++)
        #pragma unroll
        for (int q = 0; q < 4; q++) acc[i][q] = 0.f;

    #pragma unroll 1
    for (int sc = 0; sc < 4; sc++) {
        if (sc == 0)      asm volatile("cp.async.wait_group 2;" ::: "memory");
        else if (sc == 1) asm volatile("cp.async.wait_group 2;" ::: "memory");
        else if (sc == 2) asm volatile("cp.async.wait_group 1;" ::: "memory");
        else              asm volatile("cp.async.wait_group 0;" ::: "memory");
        __syncthreads();

        const uint32_t stb = sbase + (uint32_t)(sc % 3) * STAGE_STRIDE;
        const uint32_t Ab = stb;
        const uint32_t Bb = stb + 16384u;

        #pragma unroll
        for (int kk = 0; kk < 4; kk++) {
            const int c8 = 2 * kk;
            uint32_t ah[4][4], bh[2][4];
            #pragma unroll
            for (int q = 0; q < 2; q++)
                ldm4(bh[q], ldm_addr(Bb, wn * 32 + q * 16, c8, lane));
            #pragma unroll
            for (int mt = 0; mt < 4; mt++)
                ldm4(ah[mt], ldm_addr(Ab, wm * 64 + mt * 16, c8, lane));

            #pragma unroll
            for (int mt = 0; mt < 4; mt++)
                #pragma unroll
                for (int nt = 0; nt < 4; nt++) {
                    uint32_t h0 = bh[nt >> 1][nt & 1], h1 = bh[nt >> 1][(nt & 1) + 2];
                    mma16816(acc[mt * 4 + nt], ah[mt], h0, h1);
                }
        }

        if (sc == 0) {
            __syncthreads();
            issue(3, 0);
        }
    }

    const bool has_bias = (j0 < DD);
    #pragma unroll
    for (int nt = 0; nt < 4; nt++) {
        int colg = j0 + wn * 32 + nt * 8 + (lane & 3) * 2;
        float bv0 = 0.f, bv1 = 0.f;
        if (has_bias) { bv0 = __ldg(&b1[colg]); bv1 = __ldg(&b1[colg + 1]); }
        #pragma unroll
        for (int mt = 0; mt < 4; mt++) {
            float* cc = acc[mt * 4 + nt];
            int r0 = m0 + wm * 64 + mt * 16 + (lane >> 2);
            if (r0 < NN)
                *(__half2*)(g_ABh + (size_t)r0 * TWO_D + colg) =
                    __floats2half2_rn(cc[0] + bv0, cc[1] + bv1);
            if (r0 + 8 < NN)
                *(__half2*)(g_ABh + (size_t)(r0 + 8) * TWO_D + colg) =
                    __floats2half2_rn(cc[2] + bv0, cc[3] + bv1);
        }
    }
}

// ---------------------------------------------------------------------------
// Edge kernel: 8 edges per warp iteration, all 16 row-loads up front (MLP 16).
//   out[e] = sum_d w2[d] * relu(A'[src][d] + B[dst][d]) + b2
// add+relu in half2, dot in fp32.
// ---------------------------------------------------------------------------
__device__ __forceinline__ float dot8h(uint4 av, uint4 cv, float4 wA, float4 wB) {
    const __half2* a = (const __half2*)&av;
    const __half2* c = (const __half2*)&cv;
    const __half2 z2 = __float2half2_rn(0.f);
    __half2 h0 = __hmax2(__hadd2(a[0], c[0]), z2);
    __half2 h1 = __hmax2(__hadd2(a[1], c[1]), z2);
    __half2 h2 = __hmax2(__hadd2(a[2], c[2]), z2);
    __half2 h3 = __hmax2(__hadd2(a[3], c[3]), z2);
    float2 f0 = __half22float2(h0);
    float2 f1 = __half22float2(h1);
    float2 f2 = __half22float2(h2);
    float2 f3 = __half22float2(h3);
    float acc;
    acc  = f0.x * wA.x;
    acc  = fmaf(f0.y, wA.y, acc);
    acc  = fmaf(f1.x, wA.z, acc);
    acc  = fmaf(f1.y, wA.w, acc);
    acc  = fmaf(f2.x, wB.x, acc);
    acc  = fmaf(f2.y, wB.y, acc);
    acc  = fmaf(f3.x, wB.z, acc);
    acc  = fmaf(f3.y, wB.w, acc);
    return acc;
}

template <bool IS64>
__device__ __forceinline__ void edge_loop(const void* ei_raw,
                                          const float* w2,
                                          const float* b2,
                                          float* out,
                                          int lane, int warp, int nwarps) {
    const float4 wA = __ldg((const float4*)w2 + 2 * lane);
    const float4 wB = __ldg((const float4*)w2 + 2 * lane + 1);
    const float  b2v = __ldg(b2);

    const int*       ei32 = (const int*)ei_raw;
    const long long* ei64 = (const long long*)ei_raw;

    const int q = lane >> 3;           // 0..3
    const bool writer = (lane & 7) == 0;

    // EE % 8 == 0, so e0..e0+7 always valid.
    for (int e0 = warp * 8; e0 < EE; e0 += nwarps * 8) {
        int s[8], d[8];
        #pragma unroll
        for (int u = 0; u < 8; u++) {
            if (IS64) { s[u] = (int)ei64[e0 + u]; d[u] = (int)ei64[EE + e0 + u]; }
            else      { s[u] = ei32[e0 + u];      d[u] = ei32[EE + e0 + u]; }
        }

        // Issue all 16 loads before any compute (MLP 16).
        uint4 av[8], cv[8];
        #pragma unroll
        for (int u = 0; u < 8; u++) {
            av[u] = __ldg((const uint4*)(g_ABh + (size_t)s[u] * TWO_D) + lane);
            cv[u] = __ldg((const uint4*)(g_ABh + (size_t)d[u] * TWO_D + DD) + lane);
        }

        float r[8];
        #pragma unroll
        for (int u = 0; u < 8; u++)
            r[u] = dot8h(av[u], cv[u], wA, wB);

        // Fold 16, 8 on each partial
        #pragma unroll
        for (int u = 0; u < 8; u++)
            r[u] += __shfl_xor_sync(0xFFFFFFFFu, r[u], 16);
        #pragma unroll
        for (int u = 0; u < 8; u++)
            r[u] += __shfl_xor_sync(0xFFFFFFFFu, r[u], 8);

        // Two selected values per lane: edges q and 4+q
        float v0 = (q == 0) ? r[0] : (q == 1) ? r[1] : (q == 2) ? r[2] : r[3];
        float v1 = (q == 0) ? r[4] : (q == 1) ? r[5] : (q == 2) ? r[6] : r[7];
        #pragma unroll
        for (int o = 4; o > 0; o >>= 1) {
            v0 += __shfl_xor_sync(0xFFFFFFFFu, v0, o);
            v1 += __shfl_xor_sync(0xFFFFFFFFu, v1, o);
        }

        if (writer) {
            out[e0 + q]     = v0 + b2v;
            out[e0 + 4 + q] = v1 + b2v;
        }
    }
}

__global__ __launch_bounds__(256)
void edge_kernel(const void* __restrict__ ei_raw,
                 const float* __restrict__ w2,
                 const float* __restrict__ b2,
                 float* __restrict__ out) {
    const int lane   = threadIdx.x & 31;
    const int warp   = (blockIdx.x * blockDim.x + threadIdx.x) >> 5;
    const int nwarps = (gridDim.x * blockDim.x) >> 5;

    if (g_idx_is64)
        edge_loop<true>(ei_raw, w2, b2, out, lane, warp, nwarps);
    else
        edge_loop<false>(ei_raw, w2, b2, out, lane, warp, nwarps);
}

// ---------------------------------------------------------------------------
extern "C" void kernel_launch(void* const* d_in, const int* in_sizes, int n_in,
                              void* d_out, int out_size) {
    const float* z  = (const float*)d_in[0];
    const void*  ei = d_in[1];
    const float* w1 = (const float*)d_in[2];
    const float* b1 = (const float*)d_in[3];
    const float* w2 = (const float*)d_in[4];
    const float* b2 = (const float*)d_in[5];
    float*       out = (float*)d_out;

    cudaFuncSetAttribute(node_gemm_mma, cudaFuncAttributeMaxDynamicSharedMemorySize,
                         SM_GEMM_TOTAL);

    convert_all_kernel<<<2048, 256>>>(z, w1, (const int*)ei);

    dim3 ggrid((NN + 127) / 128, 4);   // 391 x 4
    node_gemm_mma<<<ggrid, 256, SM_GEMM_TOTAL>>>(b1);

    edge_kernel<<<1184, 256>>>(ei, w2, b2, out);
}

// round 14
// speedup vs baseline: 1.9124x; 1.0176x over previous
#include <cuda_runtime.h>
#include <cuda_bf16.h>
#include <cuda_fp16.h>
#include <cstdint>

// Problem constants (fixed by the dataset)
#define NN     50000
#define DD     256
#define TWO_D  512
#define EE     320000

// ---------------------------------------------------------------------------
// Scratch (static device arrays; no allocation allowed)
// ---------------------------------------------------------------------------
__device__ __half g_ABh[(size_t)NN * TWO_D];     // per-node A'|B in fp16
__device__ __half g_zf[(size_t)NN * DD];         // z in fp16, row-major [n][k]
__device__ __half g_wf[(size_t)TWO_D * DD];      // W in fp16, row-major [j][k]
__device__ int g_idx_is64;

// ---------------------------------------------------------------------------
// Fused prep kernel: z->fp16, W->fp16 (gathered layout), dtype detect.
// Two elements per loop iteration for memory-level parallelism.
// ---------------------------------------------------------------------------
#define ZT (NN * 64)        // z float4 count: 3,200,000
#define WT (TWO_D * 64)     // W float4 count: 32,768

__device__ __forceinline__ void convert_one(int i, const float* z, const float* w1) {
    if (i < ZT) {
        float4 v = ((const float4*)z)[i];
        __half2 h01 = __floats2half2_rn(v.x, v.y);
        __half2 h23 = __floats2half2_rn(v.z, v.w);
        uint2 o;
        memcpy(&o.x, &h01, 4); memcpy(&o.y, &h23, 4);
        ((uint2*)g_zf)[i] = o;
    } else {
        int i4 = i - ZT;
        int j  = i4 >> 6;
        int k  = (i4 & 63) << 2;
        const float* src = (j < DD) ? (w1 + (size_t)j * TWO_D + k)
                                    : (w1 + (size_t)(j - DD) * TWO_D + DD + k);
        float4 v = *(const float4*)src;
        __half2 h01 = __floats2half2_rn(v.x, v.y);
        __half2 h23 = __floats2half2_rn(v.z, v.w);
        uint2 o;
        memcpy(&o.x, &h01, 4); memcpy(&o.y, &h23, 4);
        ((uint2*)g_wf)[i4] = o;
    }
}

__global__ void convert_all_kernel(const float* __restrict__ z,
                                   const float* __restrict__ w1,
                                   const int* __restrict__ ei_words) {
    const int stride = gridDim.x * blockDim.x;
    const int total  = ZT + WT;
    for (int i = blockIdx.x * blockDim.x + threadIdx.x; i < total; i += 2 * stride) {
        convert_one(i, z, w1);
        int i2 = i + stride;
        if (i2 < total) convert_one(i2, z, w1);
    }
    if (blockIdx.x == 0 && threadIdx.x < 32) {
        int found = 0;
        for (int i = threadIdx.x; i < 1024; i += 32) {
            int pos = 2 * (i * (EE / 1024)) + 1;
            if (ei_words[pos] != 0) found = 1;
        }
        unsigned any = __any_sync(0xFFFFFFFFu, found);
        if (threadIdx.x == 0) g_idx_is64 = any ? 0 : 1;
    }
}

// ---------------------------------------------------------------------------
// mma.sync helpers (sm_80+, target-independent)
// ---------------------------------------------------------------------------
__device__ __forceinline__ uint32_t smem_u32(const void* p) {
    uint32_t a;
    asm("{ .reg .u64 t; cvta.to.shared.u64 t, %1; cvt.u32.u64 %0, t; }" : "=r"(a) : "l"(p));
    return a;
}
__device__ __forceinline__ void ldm4(uint32_t* r, uint32_t addr) {
    asm volatile("ldmatrix.sync.aligned.m8n8.x4.shared.b16 {%0,%1,%2,%3}, [%4];"
                 : "=r"(r[0]), "=r"(r[1]), "=r"(r[2]), "=r"(r[3]) : "r"(addr));
}
__device__ __forceinline__ void mma16816(float* c, const uint32_t* a, uint32_t b0, uint32_t b1) {
    asm volatile("mma.sync.aligned.m16n8k16.row.col.f32.f16.f16.f32 "
                 "{%0,%1,%2,%3}, {%4,%5,%6,%7}, {%8,%9}, {%0,%1,%2,%3};"
                 : "+f"(c[0]), "+f"(c[1]), "+f"(c[2]), "+f"(c[3])
                 : "r"(a[0]), "r"(a[1]), "r"(a[2]), "r"(a[3]), "r"(b0), "r"(b1));
}
__device__ __forceinline__ void cp16(uint32_t dst, const void* src) {
    asm volatile("cp.async.cg.shared.global [%0], [%1], 16;" :: "r"(dst), "l"(src));
}

__device__ __forceinline__ uint32_t tile_off(int row, int c) {
    return row * 128 + ((c ^ (row & 7)) << 4);
}
__device__ __forceinline__ uint32_t ldm_addr(uint32_t base, int m, int c8, int lane) {
    int g = lane >> 3;
    int row = m + (lane & 7) + ((g & 1) << 3);
    int c = c8 + (g >> 1);
    return base + tile_off(row, c);
}

// ---------------------------------------------------------------------------
// Node GEMM: g_ABh[50000,512] = fp16(z @ W^T (+ b1 cols<256))
// Grid 391x4, CTA tile 128x128. Superchunk = K 64. Stage 32KB, 3-stage ring.
// 8 warps, warp tile 64x32. Single-pass fp16 MMA, fp32 accumulate.
// Register double-buffered ldmatrix fragments across k16 steps.
// ---------------------------------------------------------------------------
#define STAGE_STRIDE 32768
#define SM_GEMM_TOTAL 98304

__global__ __launch_bounds__(256, 2)
void node_gemm_mma(const float* __restrict__ b1) {
    extern __shared__ __align__(128) char smem[];
    const uint32_t sbase = smem_u32(smem);
    const int tid  = threadIdx.x;
    const int lane = tid & 31;
    const int wid  = tid >> 5;
    const int wm   = wid >> 2;
    const int wn   = wid & 3;
    const int m0   = blockIdx.x * 128;
    const int j0   = blockIdx.y * 128;

    const uint32_t rbase = (uint32_t)(tid >> 3);
    const uint32_t dst0  = rbase * 128u +
        ((((uint32_t)tid & 7u) ^ (rbase & 7u)) << 4);
    const char* zb2 = (const char*)g_zf + (((uint32_t)tid & 7u) << 4);
    const char* wb2 = (const char*)g_wf + (((uint32_t)tid & 7u) << 4);

    const char* asrc[4];
    #pragma unroll
    for (int i = 0; i < 4; i++) {
        uint32_t gr = (uint32_t)m0 + rbase + 32u * i;
        if (gr >= NN) gr = NN - 1;
        asrc[i] = zb2 + (size_t)gr * 512u;
    }
    const char* bsrc[4];
    #pragma unroll
    for (int i = 0; i < 4; i++)
        bsrc[i] = wb2 + (size_t)(j0 + (int)(rbase + 32u * i)) * 512u;

    auto issue = [&](int sc, int s) {
        uint32_t stb = sbase + (uint32_t)s * STAGE_STRIDE;
        uint32_t off = (uint32_t)sc * 128u;
        #pragma unroll
        for (int i = 0; i < 4; i++)
            cp16(stb + dst0 + i * 4096u, asrc[i] + off);
        #pragma unroll
        for (int i = 0; i < 4; i++)
            cp16(stb + 16384u + dst0 + i * 4096u, bsrc[i] + off);
        asm volatile("cp.async.commit_group;" ::: "memory");
    };

    issue(0, 0);
    issue(1, 1);
    issue(2, 2);

    float acc[16][4];
    #pragma unroll
    for (int i = 0; i < 16; i++)
        #pragma unroll
        for (int q = 0; q < 4; q++) acc[i][q] = 0.f;

    // Double-buffered fragments
    uint32_t ah[2][4][4], bh[2][2][4];

    #pragma unroll 1
    for (int sc = 0; sc < 4; sc++) {
        if (sc == 0)      asm volatile("cp.async.wait_group 2;" ::: "memory");
        else if (sc == 1) asm volatile("cp.async.wait_group 2;" ::: "memory");
        else if (sc == 2) asm volatile("cp.async.wait_group 1;" ::: "memory");
        else              asm volatile("cp.async.wait_group 0;" ::: "memory");
        __syncthreads();

        const uint32_t stb = sbase + (uint32_t)(sc % 3) * STAGE_STRIDE;
        const uint32_t Ab = stb;
        const uint32_t Bb = stb + 16384u;

        // Prime buffer 0 with kk=0 fragments
        #pragma unroll
        for (int q = 0; q < 2; q++)
            ldm4(bh[0][q], ldm_addr(Bb, wn * 32 + q * 16, 0, lane));
        #pragma unroll
        for (int mt = 0; mt < 4; mt++)
            ldm4(ah[0][mt], ldm_addr(Ab, wm * 64 + mt * 16, 0, lane));

        #pragma unroll
        for (int kk = 0; kk < 4; kk++) {
            const int cur = kk & 1;
            const int nxt = cur ^ 1;
            if (kk < 3) {
                const int c8n = 2 * (kk + 1);
                #pragma unroll
                for (int q = 0; q < 2; q++)
                    ldm4(bh[nxt][q], ldm_addr(Bb, wn * 32 + q * 16, c8n, lane));
                #pragma unroll
                for (int mt = 0; mt < 4; mt++)
                    ldm4(ah[nxt][mt], ldm_addr(Ab, wm * 64 + mt * 16, c8n, lane));
            }
            #pragma unroll
            for (int mt = 0; mt < 4; mt++)
                #pragma unroll
                for (int nt = 0; nt < 4; nt++) {
                    uint32_t h0 = bh[cur][nt >> 1][nt & 1];
                    uint32_t h1 = bh[cur][nt >> 1][(nt & 1) + 2];
                    mma16816(acc[mt * 4 + nt], ah[cur][mt], h0, h1);
                }
        }

        if (sc == 0) {
            __syncthreads();
            issue(3, 0);
        }
    }

    const bool has_bias = (j0 < DD);
    #pragma unroll
    for (int nt = 0; nt < 4; nt++) {
        int colg = j0 + wn * 32 + nt * 8 + (lane & 3) * 2;
        float bv0 = 0.f, bv1 = 0.f;
        if (has_bias) { bv0 = __ldg(&b1[colg]); bv1 = __ldg(&b1[colg + 1]); }
        #pragma unroll
        for (int mt = 0; mt < 4; mt++) {
            float* cc = acc[mt * 4 + nt];
            int r0 = m0 + wm * 64 + mt * 16 + (lane >> 2);
            if (r0 < NN)
                *(__half2*)(g_ABh + (size_t)r0 * TWO_D + colg) =
                    __floats2half2_rn(cc[0] + bv0, cc[1] + bv1);
            if (r0 + 8 < NN)
                *(__half2*)(g_ABh + (size_t)(r0 + 8) * TWO_D + colg) =
                    __floats2half2_rn(cc[2] + bv0, cc[3] + bv1);
        }
    }
}

// ---------------------------------------------------------------------------
// Edge kernel: 8 edges per warp iteration, all 16 row-loads up front (MLP 16).
//   out[e] = sum_d w2[d] * relu(A'[src][d] + B[dst][d]) + b2
// add+relu in half2, dot in fp32.
// ---------------------------------------------------------------------------
__device__ __forceinline__ float dot8h(uint4 av, uint4 cv, float4 wA, float4 wB) {
    const __half2* a = (const __half2*)&av;
    const __half2* c = (const __half2*)&cv;
    const __half2 z2 = __float2half2_rn(0.f);
    __half2 h0 = __hmax2(__hadd2(a[0], c[0]), z2);
    __half2 h1 = __hmax2(__hadd2(a[1], c[1]), z2);
    __half2 h2 = __hmax2(__hadd2(a[2], c[2]), z2);
    __half2 h3 = __hmax2(__hadd2(a[3], c[3]), z2);
    float2 f0 = __half22float2(h0);
    float2 f1 = __half22float2(h1);
    float2 f2 = __half22float2(h2);
    float2 f3 = __half22float2(h3);
    float acc;
    acc  = f0.x * wA.x;
    acc  = fmaf(f0.y, wA.y, acc);
    acc  = fmaf(f1.x, wA.z, acc);
    acc  = fmaf(f1.y, wA.w, acc);
    acc  = fmaf(f2.x, wB.x, acc);
    acc  = fmaf(f2.y, wB.y, acc);
    acc  = fmaf(f3.x, wB.z, acc);
    acc  = fmaf(f3.y, wB.w, acc);
    return acc;
}

template <bool IS64>
__device__ __forceinline__ void edge_loop(const void* ei_raw,
                                          const float* w2,
                                          const float* b2,
                                          float* out,
                                          int lane, int warp, int nwarps) {
    const float4 wA = __ldg((const float4*)w2 + 2 * lane);
    const float4 wB = __ldg((const float4*)w2 + 2 * lane + 1);
    const float  b2v = __ldg(b2);

    const int*       ei32 = (const int*)ei_raw;
    const long long* ei64 = (const long long*)ei_raw;

    const int q = lane >> 3;
    const bool writer = (lane & 7) == 0;

    for (int e0 = warp * 8; e0 < EE; e0 += nwarps * 8) {
        int s[8], d[8];
        #pragma unroll
        for (int u = 0; u < 8; u++) {
            if (IS64) { s[u] = (int)ei64[e0 + u]; d[u] = (int)ei64[EE + e0 + u]; }
            else      { s[u] = ei32[e0 + u];      d[u] = ei32[EE + e0 + u]; }
        }

        uint4 av[8], cv[8];
        #pragma unroll
        for (int u = 0; u < 8; u++) {
            av[u] = __ldg((const uint4*)(g_ABh + (size_t)s[u] * TWO_D) + lane);
            cv[u] = __ldg((const uint4*)(g_ABh + (size_t)d[u] * TWO_D + DD) + lane);
        }

        float r[8];
        #pragma unroll
        for (int u = 0; u < 8; u++)
            r[u] = dot8h(av[u], cv[u], wA, wB);

        #pragma unroll
        for (int u = 0; u < 8; u++)
            r[u] += __shfl_xor_sync(0xFFFFFFFFu, r[u], 16);
        #pragma unroll
        for (int u = 0; u < 8; u++)
            r[u] += __shfl_xor_sync(0xFFFFFFFFu, r[u], 8);

        float v0 = (q == 0) ? r[0] : (q == 1) ? r[1] : (q == 2) ? r[2] : r[3];
        float v1 = (q == 0) ? r[4] : (q == 1) ? r[5] : (q == 2) ? r[6] : r[7];
        #pragma unroll
        for (int o = 4; o > 0; o >>= 1) {
            v0 += __shfl_xor_sync(0xFFFFFFFFu, v0, o);
            v1 += __shfl_xor_sync(0xFFFFFFFFu, v1, o);
        }

        if (writer) {
            out[e0 + q]     = v0 + b2v;
            out[e0 + 4 + q] = v1 + b2v;
        }
    }
}

__global__ __launch_bounds__(256)
void edge_kernel(const void* __restrict__ ei_raw,
                 const float* __restrict__ w2,
                 const float* __restrict__ b2,
                 float* __restrict__ out) {
    const int lane   = threadIdx.x & 31;
    const int warp   = (blockIdx.x * blockDim.x + threadIdx.x) >> 5;
    const int nwarps = (gridDim.x * blockDim.x) >> 5;

    if (g_idx_is64)
        edge_loop<true>(ei_raw, w2, b2, out, lane, warp, nwarps);
    else
        edge_loop<false>(ei_raw, w2, b2, out, lane, warp, nwarps);
}

// ---------------------------------------------------------------------------
extern "C" void kernel_launch(void* const* d_in, const int* in_sizes, int n_in,
                              void* d_out, int out_size) {
    const float* z  = (const float*)d_in[0];
    const void*  ei = d_in[1];
    const float* w1 = (const float*)d_in[2];
    const float* b1 = (const float*)d_in[3];
    const float* w2 = (const float*)d_in[4];
    const float* b2 = (const float*)d_in[5];
    float*       out = (float*)d_out;

    cudaFuncSetAttribute(node_gemm_mma, cudaFuncAttributeMaxDynamicSharedMemorySize,
                         SM_GEMM_TOTAL);

    convert_all_kernel<<<2048, 256>>>(z, w1, (const int*)ei);

    dim3 ggrid((NN + 127) / 128, 4);   // 391 x 4
    node_gemm_mma<<<ggrid, 256, SM_GEMM_TOTAL>>>(b1);

    edge_kernel<<<1184, 256>>>(ei, w2, b2, out);
}

// round 15
// speedup vs baseline: 1.9592x; 1.0245x over previous
#include <cuda_runtime.h>
#include <cuda_bf16.h>
#include <cuda_fp16.h>
#include <cstdint>

// Problem constants (fixed by the dataset)
#define NN     50000
#define DD     256
#define TWO_D  512
#define EE     320000

// ---------------------------------------------------------------------------
// Scratch (static device arrays; no allocation allowed)
// ---------------------------------------------------------------------------
__device__ __half g_ABh[(size_t)NN * TWO_D];     // per-node A'|B in fp16
__device__ __half g_zf[(size_t)NN * DD];         // z in fp16, row-major [n][k]
__device__ __half g_wf[(size_t)TWO_D * DD];      // W in fp16, row-major [j][k]
__device__ int g_idx_is64;

// ---------------------------------------------------------------------------
// Fused prep kernel: z->fp16, W->fp16 (gathered layout), dtype detect.
// 8-float granularity: 2x float4 loads -> 1x uint4 (16B) store.
// Two units per loop iteration -> 4 loads in flight per thread.
// ---------------------------------------------------------------------------
#define ZT8 (NN * 32)        // z 8-float units: 1,600,000
#define WT8 (TWO_D * 32)     // W 8-float units: 16,384

__device__ __forceinline__ uint4 cvt8(float4 v0, float4 v1) {
    __half2 a = __floats2half2_rn(v0.x, v0.y);
    __half2 b = __floats2half2_rn(v0.z, v0.w);
    __half2 c = __floats2half2_rn(v1.x, v1.y);
    __half2 d = __floats2half2_rn(v1.z, v1.w);
    uint4 o;
    memcpy(&o.x, &a, 4); memcpy(&o.y, &b, 4);
    memcpy(&o.z, &c, 4); memcpy(&o.w, &d, 4);
    return o;
}

__device__ __forceinline__ void convert_unit(int i, const float* z, const float* w1) {
    if (i < ZT8) {
        float4 v0 = ((const float4*)z)[2 * i];
        float4 v1 = ((const float4*)z)[2 * i + 1];
        ((uint4*)g_zf)[i] = cvt8(v0, v1);
    } else {
        int i8 = i - ZT8;
        int j  = i8 >> 5;            // 0..511  (32 units per 256-half row)
        int k  = (i8 & 31) << 3;     // 0..248 step 8
        // W[j][k..k+7]: j<256 -> w1[j*512+k]; j>=256 -> w1[(j-256)*512+256+k]
        const float* src = (j < DD) ? (w1 + (size_t)j * TWO_D + k)
                                    : (w1 + (size_t)(j - DD) * TWO_D + DD + k);
        float4 v0 = ((const float4*)src)[0];
        float4 v1 = ((const float4*)src)[1];
        ((uint4*)g_wf)[i8] = cvt8(v0, v1);
    }
}

__global__ void convert_all_kernel(const float* __restrict__ z,
                                   const float* __restrict__ w1,
                                   const int* __restrict__ ei_words) {
    const int stride = gridDim.x * blockDim.x;
    const int total  = ZT8 + WT8;
    for (int i = blockIdx.x * blockDim.x + threadIdx.x; i < total; i += 2 * stride) {
        convert_unit(i, z, w1);
        int i2 = i + stride;
        if (i2 < total) convert_unit(i2, z, w1);
    }
    // Inline dtype detect (int64 -> odd 32-bit words all zero for idx < 2^31)
    if (blockIdx.x == 0 && threadIdx.x < 32) {
        int found = 0;
        for (int i = threadIdx.x; i < 1024; i += 32) {
            int pos = 2 * (i * (EE / 1024)) + 1;
            if (ei_words[pos] != 0) found = 1;
        }
        unsigned any = __any_sync(0xFFFFFFFFu, found);
        if (threadIdx.x == 0) g_idx_is64 = any ? 0 : 1;
    }
}

// ---------------------------------------------------------------------------
// mma.sync helpers (sm_80+, target-independent)
// ---------------------------------------------------------------------------
__device__ __forceinline__ uint32_t smem_u32(const void* p) {
    uint32_t a;
    asm("{ .reg .u64 t; cvta.to.shared.u64 t, %1; cvt.u32.u64 %0, t; }" : "=r"(a) : "l"(p));
    return a;
}
__device__ __forceinline__ void ldm4(uint32_t* r, uint32_t addr) {
    asm volatile("ldmatrix.sync.aligned.m8n8.x4.shared.b16 {%0,%1,%2,%3}, [%4];"
                 : "=r"(r[0]), "=r"(r[1]), "=r"(r[2]), "=r"(r[3]) : "r"(addr));
}
__device__ __forceinline__ void mma16816(float* c, const uint32_t* a, uint32_t b0, uint32_t b1) {
    asm volatile("mma.sync.aligned.m16n8k16.row.col.f32.f16.f16.f32 "
                 "{%0,%1,%2,%3}, {%4,%5,%6,%7}, {%8,%9}, {%0,%1,%2,%3};"
                 : "+f"(c[0]), "+f"(c[1]), "+f"(c[2]), "+f"(c[3])
                 : "r"(a[0]), "r"(a[1]), "r"(a[2]), "r"(a[3]), "r"(b0), "r"(b1));
}
__device__ __forceinline__ void cp16(uint32_t dst, const void* src) {
    asm volatile("cp.async.cg.shared.global [%0], [%1], 16;" :: "r"(dst), "l"(src));
}

__device__ __forceinline__ uint32_t tile_off(int row, int c) {
    return row * 128 + ((c ^ (row & 7)) << 4);
}
__device__ __forceinline__ uint32_t ldm_addr(uint32_t base, int m, int c8, int lane) {
    int g = lane >> 3;
    int row = m + (lane & 7) + ((g & 1) << 3);
    int c = c8 + (g >> 1);
    return base + tile_off(row, c);
}

// ---------------------------------------------------------------------------
// Node GEMM: g_ABh[50000,512] = fp16(z @ W^T (+ b1 cols<256))
// Grid 391x4, CTA tile 128x128. Superchunk = K 64. Stage 32KB, 3-stage ring.
// 8 warps, warp tile 64x32. Single-pass fp16 MMA, fp32 accumulate.
// Register double-buffered ldmatrix fragments across k16 steps.
// ---------------------------------------------------------------------------
#define STAGE_STRIDE 32768
#define SM_GEMM_TOTAL 98304

__global__ __launch_bounds__(256, 2)
void node_gemm_mma(const float* __restrict__ b1) {
    extern __shared__ __align__(128) char smem[];
    const uint32_t sbase = smem_u32(smem);
    const int tid  = threadIdx.x;
    const int lane = tid & 31;
    const int wid  = tid >> 5;
    const int wm   = wid >> 2;
    const int wn   = wid & 3;
    const int m0   = blockIdx.x * 128;
    const int j0   = blockIdx.y * 128;

    const uint32_t rbase = (uint32_t)(tid >> 3);
    const uint32_t dst0  = rbase * 128u +
        ((((uint32_t)tid & 7u) ^ (rbase & 7u)) << 4);
    const char* zb2 = (const char*)g_zf + (((uint32_t)tid & 7u) << 4);
    const char* wb2 = (const char*)g_wf + (((uint32_t)tid & 7u) << 4);

    const char* asrc[4];
    #pragma unroll
    for (int i = 0; i < 4; i++) {
        uint32_t gr = (uint32_t)m0 + rbase + 32u * i;
        if (gr >= NN) gr = NN - 1;
        asrc[i] = zb2 + (size_t)gr * 512u;
    }
    const char* bsrc[4];
    #pragma unroll
    for (int i = 0; i < 4; i++)
        bsrc[i] = wb2 + (size_t)(j0 + (int)(rbase + 32u * i)) * 512u;

    auto issue = [&](int sc, int s) {
        uint32_t stb = sbase + (uint32_t)s * STAGE_STRIDE;
        uint32_t off = (uint32_t)sc * 128u;
        #pragma unroll
        for (int i = 0; i < 4; i++)
            cp16(stb + dst0 + i * 4096u, asrc[i] + off);
        #pragma unroll
        for (int i = 0; i < 4; i++)
            cp16(stb + 16384u + dst0 + i * 4096u, bsrc[i] + off);
        asm volatile("cp.async.commit_group;" ::: "memory");
    };

    issue(0, 0);
    issue(1, 1);
    issue(2, 2);

    float acc[16][4];
    #pragma unroll
    for (int i = 0; i < 16; i++)
        #pragma unroll
        for (int q = 0; q < 4; q++) acc[i][q] = 0.f;

    // Double-buffered fragments
    uint32_t ah[2][4][4], bh[2][2][4];

    #pragma unroll 1
    for (int sc = 0; sc < 4; sc++) {
        if (sc == 0)      asm volatile("cp.async.wait_group 2;" ::: "memory");
        else if (sc == 1) asm volatile("cp.async.wait_group 2;" ::: "memory");
        else if (sc == 2) asm volatile("cp.async.wait_group 1;" ::: "memory");
        else              asm volatile("cp.async.wait_group 0;" ::: "memory");
        __syncthreads();

        const uint32_t stb = sbase + (uint32_t)(sc % 3) * STAGE_STRIDE;
        const uint32_t Ab = stb;
        const uint32_t Bb = stb + 16384u;

        // Prime buffer 0 with kk=0 fragments
        #pragma unroll
        for (int q = 0; q < 2; q++)
            ldm4(bh[0][q], ldm_addr(Bb, wn * 32 + q * 16, 0, lane));
        #pragma unroll
        for (int mt = 0; mt < 4; mt++)
            ldm4(ah[0][mt], ldm_addr(Ab, wm * 64 + mt * 16, 0, lane));

        #pragma unroll
        for (int kk = 0; kk < 4; kk++) {
            const int cur = kk & 1;
            const int nxt = cur ^ 1;
            if (kk < 3) {
                const int c8n = 2 * (kk + 1);
                #pragma unroll
                for (int q = 0; q < 2; q++)
                    ldm4(bh[nxt][q], ldm_addr(Bb, wn * 32 + q * 16, c8n, lane));
                #pragma unroll
                for (int mt = 0; mt < 4; mt++)
                    ldm4(ah[nxt][mt], ldm_addr(Ab, wm * 64 + mt * 16, c8n, lane));
            }
            #pragma unroll
            for (int mt = 0; mt < 4; mt++)
                #pragma unroll
                for (int nt = 0; nt < 4; nt++) {
                    uint32_t h0 = bh[cur][nt >> 1][nt & 1];
                    uint32_t h1 = bh[cur][nt >> 1][(nt & 1) + 2];
                    mma16816(acc[mt * 4 + nt], ah[cur][mt], h0, h1);
                }
        }

        if (sc == 0) {
            __syncthreads();
            issue(3, 0);
        }
    }

    const bool has_bias = (j0 < DD);
    #pragma unroll
    for (int nt = 0; nt < 4; nt++) {
        int colg = j0 + wn * 32 + nt * 8 + (lane & 3) * 2;
        float bv0 = 0.f, bv1 = 0.f;
        if (has_bias) { bv0 = __ldg(&b1[colg]); bv1 = __ldg(&b1[colg + 1]); }
        #pragma unroll
        for (int mt = 0; mt < 4; mt++) {
            float* cc = acc[mt * 4 + nt];
            int r0 = m0 + wm * 64 + mt * 16 + (lane >> 2);
            if (r0 < NN)
                *(__half2*)(g_ABh + (size_t)r0 * TWO_D + colg) =
                    __floats2half2_rn(cc[0] + bv0, cc[1] + bv1);
            if (r0 + 8 < NN)
                *(__half2*)(g_ABh + (size_t)(r0 + 8) * TWO_D + colg) =
                    __floats2half2_rn(cc[2] + bv0, cc[3] + bv1);
        }
    }
}

// ---------------------------------------------------------------------------
// Edge kernel: 8 edges per warp iteration, all 16 row-loads up front (MLP 16).
//   out[e] = sum_d w2[d] * relu(A'[src][d] + B[dst][d]) + b2
// add+relu in half2, dot in fp32.
// ---------------------------------------------------------------------------
__device__ __forceinline__ float dot8h(uint4 av, uint4 cv, float4 wA, float4 wB) {
    const __half2* a = (const __half2*)&av;
    const __half2* c = (const __half2*)&cv;
    const __half2 z2 = __float2half2_rn(0.f);
    __half2 h0 = __hmax2(__hadd2(a[0], c[0]), z2);
    __half2 h1 = __hmax2(__hadd2(a[1], c[1]), z2);
    __half2 h2 = __hmax2(__hadd2(a[2], c[2]), z2);
    __half2 h3 = __hmax2(__hadd2(a[3], c[3]), z2);
    float2 f0 = __half22float2(h0);
    float2 f1 = __half22float2(h1);
    float2 f2 = __half22float2(h2);
    float2 f3 = __half22float2(h3);
    float acc;
    acc  = f0.x * wA.x;
    acc  = fmaf(f0.y, wA.y, acc);
    acc  = fmaf(f1.x, wA.z, acc);
    acc  = fmaf(f1.y, wA.w, acc);
    acc  = fmaf(f2.x, wB.x, acc);
    acc  = fmaf(f2.y, wB.y, acc);
    acc  = fmaf(f3.x, wB.z, acc);
    acc  = fmaf(f3.y, wB.w, acc);
    return acc;
}

template <bool IS64>
__device__ __forceinline__ void edge_loop(const void* ei_raw,
                                          const float* w2,
                                          const float* b2,
                                          float* out,
                                          int lane, int warp, int nwarps) {
    const float4 wA = __ldg((const float4*)w2 + 2 * lane);
    const float4 wB = __ldg((const float4*)w2 + 2 * lane + 1);
    const float  b2v = __ldg(b2);

    const int*       ei32 = (const int*)ei_raw;
    const long long* ei64 = (const long long*)ei_raw;

    const int q = lane >> 3;
    const bool writer = (lane & 7) == 0;

    for (int e0 = warp * 8; e0 < EE; e0 += nwarps * 8) {
        int s[8], d[8];
        #pragma unroll
        for (int u = 0; u < 8; u++) {
            if (IS64) { s[u] = (int)ei64[e0 + u]; d[u] = (int)ei64[EE + e0 + u]; }
            else      { s[u] = ei32[e0 + u];      d[u] = ei32[EE + e0 + u]; }
        }

        uint4 av[8], cv[8];
        #pragma unroll
        for (int u = 0; u < 8; u++) {
            av[u] = __ldg((const uint4*)(g_ABh + (size_t)s[u] * TWO_D) + lane);
            cv[u] = __ldg((const uint4*)(g_ABh + (size_t)d[u] * TWO_D + DD) + lane);
        }

        float r[8];
        #pragma unroll
        for (int u = 0; u < 8; u++)
            r[u] = dot8h(av[u], cv[u], wA, wB);

        #pragma unroll
        for (int u = 0; u < 8; u++)
            r[u] += __shfl_xor_sync(0xFFFFFFFFu, r[u], 16);
        #pragma unroll
        for (int u = 0; u < 8; u++)
            r[u] += __shfl_xor_sync(0xFFFFFFFFu, r[u], 8);

        float v0 = (q == 0) ? r[0] : (q == 1) ? r[1] : (q == 2) ? r[2] : r[3];
        float v1 = (q == 0) ? r[4] : (q == 1) ? r[5] : (q == 2) ? r[6] : r[7];
        #pragma unroll
        for (int o = 4; o > 0; o >>= 1) {
            v0 += __shfl_xor_sync(0xFFFFFFFFu, v0, o);
            v1 += __shfl_xor_sync(0xFFFFFFFFu, v1, o);
        }

        if (writer) {
            out[e0 + q]     = v0 + b2v;
            out[e0 + 4 + q] = v1 + b2v;
        }
    }
}

__global__ __launch_bounds__(256)
void edge_kernel(const void* __restrict__ ei_raw,
                 const float* __restrict__ w2,
                 const float* __restrict__ b2,
                 float* __restrict__ out) {
    const int lane   = threadIdx.x & 31;
    const int warp   = (blockIdx.x * blockDim.x + threadIdx.x) >> 5;
    const int nwarps = (gridDim.x * blockDim.x) >> 5;

    if (g_idx_is64)
        edge_loop<true>(ei_raw, w2, b2, out, lane, warp, nwarps);
    else
        edge_loop<false>(ei_raw, w2, b2, out, lane, warp, nwarps);
}

// ---------------------------------------------------------------------------
extern "C" void kernel_launch(void* const* d_in, const int* in_sizes, int n_in,
                              void* d_out, int out_size) {
    const float* z  = (const float*)d_in[0];
    const void*  ei = d_in[1];
    const float* w1 = (const float*)d_in[2];
    const float* b1 = (const float*)d_in[3];
    const float* w2 = (const float*)d_in[4];
    const float* b2 = (const float*)d_in[5];
    float*       out = (float*)d_out;

    cudaFuncSetAttribute(node_gemm_mma, cudaFuncAttributeMaxDynamicSharedMemorySize,
                         SM_GEMM_TOTAL);

    convert_all_kernel<<<2048, 256>>>(z, w1, (const int*)ei);

    dim3 ggrid((NN + 127) / 128, 4);   // 391 x 4
    node_gemm_mma<<<ggrid, 256, SM_GEMM_TOTAL>>>(b1);

    edge_kernel<<<1184, 256>>>(ei, w2, b2, out);
}